// round 1
// baseline (speedup 1.0000x reference)
#include <cuda_runtime.h>
#include <math.h>

// ---------------- problem constants ----------------
// B=8, C=512, HEADS=8, DH=64, tokens=4097 (cls+4096), pad=255 -> N=4352
// landmarks m=256, l=17, pinv iters=6, res kernel 33
#define NB 8
#define CD 512
#define NHEAD 8
#define DHD 64
#define NTOK 4097
#define NPAD 4352
#define PADF 255
#define ML 256
#define LSUB 17
#define NF 4096

// ---------------- device scratch ----------------
__device__ float g_h   [8L*4097*512];
__device__ float g_h2  [8L*4097*512];
__device__ float g_xp  [8L*4352*512];
__device__ float g_qkv [8L*4352*1536];
__device__ float g_ql  [64L*256*64];
__device__ float g_kl  [64L*256*64];
__device__ float g_sim1[64L*4352*256];
__device__ float g_sim3[64L*256*4352];
__device__ float g_a2  [64L*256*256];
__device__ float g_zA  [64L*256*256];
__device__ float g_zB  [64L*256*256];
__device__ float g_xz  [64L*256*256];
__device__ float g_t1  [64L*256*256];
__device__ float g_t2  [64L*256*256];
__device__ float g_a3v [64L*256*64];
__device__ float g_tmp2[64L*256*64];
__device__ float g_oat [64L*4352*64];
__device__ float g_ac  [8L*4097*512];
__device__ float g_cnn [8L*512*4096];
__device__ float g_yp  [8L*512*4096];
__device__ float g_scal[2];

// ---------------- small kernels ----------------
__global__ void k_build_h(const float* __restrict__ feat, const float* __restrict__ cls){
    long idx = (long)blockIdx.x*256 + threadIdx.x;
    if(idx >= 8L*4097*512) return;
    int c = idx & 511; long r = idx >> 9; int t = (int)(r % 4097); int b = (int)(r / 4097);
    g_h[idx] = (t==0) ? cls[c] : feat[((long)b*4096 + (t-1))*512 + c];
}

__global__ void k_zero_pad(float* __restrict__ xp){
    long idx = (long)blockIdx.x*256 + threadIdx.x;
    if(idx >= 8L*255*512) return;
    int c = idx & 511; long r = idx >> 9; int t = (int)(r % 255); int b = (int)(r / 255);
    xp[((long)b*4352 + t)*512 + c] = 0.f;
}

__global__ void k_ln(const float* __restrict__ h, const float* __restrict__ g,
                     const float* __restrict__ be, float* __restrict__ xp){
    long r = blockIdx.x;                 // b*4097 + t
    int b = (int)(r / 4097); int t = (int)(r % 4097);
    const float* x = h + r*512;
    float* y = xp + ((long)b*4352 + 255 + t)*512;
    int tid = threadIdx.x;
    __shared__ float red[256];
    float s = 0.f;
    for(int i=tid;i<512;i+=256) s += x[i];
    red[tid]=s; __syncthreads();
    for(int k=128;k;k>>=1){ if(tid<k) red[tid]+=red[tid+k]; __syncthreads(); }
    float mean = red[0] * (1.f/512.f); __syncthreads();
    float v = 0.f;
    for(int i=tid;i<512;i+=256){ float d=x[i]-mean; v += d*d; }
    red[tid]=v; __syncthreads();
    for(int k=128;k;k>>=1){ if(tid<k) red[tid]+=red[tid+k]; __syncthreads(); }
    float rstd = rsqrtf(red[0]*(1.f/512.f) + 1e-5f);
    for(int i=tid;i<512;i+=256) y[i] = (x[i]-mean)*rstd*g[i] + be[i];
}

// ---------------- GEMMs (64x64 tile, 4x4/thread, 256 threads) ----------------
// C = alpha * A @ B^T (+bias)(+C)   A:(M,K) lda, B:(N,K) ldb   batched (b,h)
__global__ void k_gemm_nt(const float* __restrict__ A, int lda, long sAb, long sAh,
                          const float* __restrict__ Bm, int ldb, long sBb, long sBh,
                          float* __restrict__ Cm, int ldc, long sCb, long sCh,
                          int M, int N, int K, float alpha,
                          const float* __restrict__ bias, int acc)
{
    int z = blockIdx.z; int hh = z & 7; int bb = z >> 3;
    A  += (long)bb*sAb + (long)hh*sAh;
    Bm += (long)bb*sBb + (long)hh*sBh;
    Cm += (long)bb*sCb + (long)hh*sCh;
    __shared__ float As[16][65];
    __shared__ float Bs[16][65];
    int t = threadIdx.x, tx = t & 15, ty = t >> 4;
    int r0 = blockIdx.x*64, c0 = blockIdx.y*64;
    float acc4[4][4] = {};
    for(int k0=0;k0<K;k0+=16){
        #pragma unroll
        for(int i=0;i<4;i++){
            int id=t+i*256; int m=id>>4, kk=id&15;
            int gm=r0+m, gk=k0+kk;
            As[kk][m] = (gm<M && gk<K) ? A[(long)gm*lda+gk] : 0.f;
        }
        #pragma unroll
        for(int i=0;i<4;i++){
            int id=t+i*256; int n=id>>4, kk=id&15;
            int gn=c0+n, gk=k0+kk;
            Bs[kk][n] = (gn<N && gk<K) ? Bm[(long)gn*ldb+gk] : 0.f;
        }
        __syncthreads();
        #pragma unroll
        for(int kk=0;kk<16;kk++){
            float a[4], b2[4];
            #pragma unroll
            for(int i=0;i<4;i++) a[i]=As[kk][ty*4+i];
            #pragma unroll
            for(int j=0;j<4;j++) b2[j]=Bs[kk][tx*4+j];
            #pragma unroll
            for(int i=0;i<4;i++)
                #pragma unroll
                for(int j=0;j<4;j++)
                    acc4[i][j] = fmaf(a[i], b2[j], acc4[i][j]);
        }
        __syncthreads();
    }
    #pragma unroll
    for(int i=0;i<4;i++){
        int gm=r0+ty*4+i; if(gm>=M) continue;
        #pragma unroll
        for(int j=0;j<4;j++){
            int gn=c0+tx*4+j; if(gn>=N) continue;
            float v = alpha*acc4[i][j];
            if(bias) v += bias[gn];
            long o = (long)gm*ldc + gn;
            if(acc) v += Cm[o];
            Cm[o] = v;
        }
    }
}

// C = alpha * A @ B (+C)   A:(M,K) lda, B:(K,N) ldb
__global__ void k_gemm_nn(const float* __restrict__ A, int lda, long sAb, long sAh,
                          const float* __restrict__ Bm, int ldb, long sBb, long sBh,
                          float* __restrict__ Cm, int ldc, long sCb, long sCh,
                          int M, int N, int K, float alpha, int acc)
{
    int z = blockIdx.z; int hh = z & 7; int bb = z >> 3;
    A  += (long)bb*sAb + (long)hh*sAh;
    Bm += (long)bb*sBb + (long)hh*sBh;
    Cm += (long)bb*sCb + (long)hh*sCh;
    __shared__ float As[16][65];
    __shared__ float Bs[16][65];
    int t = threadIdx.x, tx = t & 15, ty = t >> 4;
    int r0 = blockIdx.x*64, c0 = blockIdx.y*64;
    float acc4[4][4] = {};
    for(int k0=0;k0<K;k0+=16){
        #pragma unroll
        for(int i=0;i<4;i++){
            int id=t+i*256; int m=id>>4, kk=id&15;
            int gm=r0+m, gk=k0+kk;
            As[kk][m] = (gm<M && gk<K) ? A[(long)gm*lda+gk] : 0.f;
        }
        #pragma unroll
        for(int i=0;i<4;i++){
            int id=t+i*256; int kk=id>>6, n=id&63;
            int gn=c0+n, gk=k0+kk;
            Bs[kk][n] = (gn<N && gk<K) ? Bm[(long)gk*ldb+gn] : 0.f;
        }
        __syncthreads();
        #pragma unroll
        for(int kk=0;kk<16;kk++){
            float a[4], b2[4];
            #pragma unroll
            for(int i=0;i<4;i++) a[i]=As[kk][ty*4+i];
            #pragma unroll
            for(int j=0;j<4;j++) b2[j]=Bs[kk][tx*4+j];
            #pragma unroll
            for(int i=0;i<4;i++)
                #pragma unroll
                for(int j=0;j<4;j++)
                    acc4[i][j] = fmaf(a[i], b2[j], acc4[i][j]);
        }
        __syncthreads();
    }
    #pragma unroll
    for(int i=0;i<4;i++){
        int gm=r0+ty*4+i; if(gm>=M) continue;
        #pragma unroll
        for(int j=0;j<4;j++){
            int gn=c0+tx*4+j; if(gn>=N) continue;
            float v = alpha*acc4[i][j];
            long o = (long)gm*ldc + gn;
            if(acc) v += Cm[o];
            Cm[o] = v;
        }
    }
}

// ---------------- softmax over rows of length L ----------------
__global__ void k_softmax(float* __restrict__ X, int L){
    long row = blockIdx.x;
    float* x = X + row*(long)L;
    int t = threadIdx.x;
    __shared__ float red[256];
    float mx = -1e30f;
    for(int i=t;i<L;i+=256) mx = fmaxf(mx, x[i]);
    red[t]=mx; __syncthreads();
    for(int k=128;k;k>>=1){ if(t<k) red[t]=fmaxf(red[t],red[t+k]); __syncthreads(); }
    mx = red[0]; __syncthreads();
    float sum = 0.f;
    for(int i=t;i<L;i+=256){ float e=__expf(x[i]-mx); x[i]=e; sum+=e; }
    red[t]=sum; __syncthreads();
    for(int k=128;k;k>>=1){ if(t<k) red[t]+=red[t+k]; __syncthreads(); }
    float inv = 1.f/red[0];
    for(int i=t;i<L;i+=256) x[i] *= inv;
}

// ---------------- landmarks (mean over 17 tokens), q scaled by 1/8 ----------------
__global__ void k_landmarks(const float* __restrict__ qkv, float* __restrict__ ql, float* __restrict__ kl){
    int idx = blockIdx.x;                   // b*8*256 + h*256 + mi
    int mi = idx % 256; int hh = (idx/256) & 7; int b = idx / (256*8);
    int dh = threadIdx.x;
    float sq=0.f, sk=0.f;
    for(int j=0;j<LSUB;j++){
        long tok = (long)mi*LSUB + j;
        const float* base = qkv + ((long)b*4352 + tok)*1536 + hh*64 + dh;
        sq += base[0];
        sk += base[512];
    }
    long o = (long)idx*64 + dh;
    ql[o] = sq * (0.125f/LSUB);
    kl[o] = sk * (1.0f/LSUB);
}

// ---------------- pinv scalar reductions ----------------
__global__ void k_scal_init(){ if(threadIdx.x < 2) g_scal[threadIdx.x] = 0.f; }

__global__ void k_rowsum_max(const float* __restrict__ X){
    long row = blockIdx.x;
    const float* x = X + row*256;
    int t = threadIdx.x;
    __shared__ float red[256];
    red[t] = fabsf(x[t]); __syncthreads();
    for(int k=128;k;k>>=1){ if(t<k) red[t]+=red[t+k]; __syncthreads(); }
    if(t==0) atomicMax((int*)&g_scal[0], __float_as_int(red[0]));
}

__global__ void k_colsum_max(const float* __restrict__ X){
    int b = blockIdx.x; int j = threadIdx.x;
    const float* x = X + (long)b*65536;
    float s = 0.f;
    for(int i=0;i<256;i++) s += fabsf(x[i*256+j]);
    __shared__ float red[256];
    red[j]=s; __syncthreads();
    for(int k=128;k;k>>=1){ if(j<k) red[j]=fmaxf(red[j],red[j+k]); __syncthreads(); }
    if(j==0) atomicMax((int*)&g_scal[1], __float_as_int(red[0]));
}

__global__ void k_tr_scale(const float* __restrict__ X, float* __restrict__ Z){
    long idx = (long)blockIdx.x*256 + threadIdx.x;
    if(idx >= 64L*65536) return;
    float inv = 1.f/(g_scal[0]*g_scal[1]);
    int j = (int)(idx & 255); int i = (int)((idx>>8) & 255); long b = idx >> 16;
    Z[idx] = X[(b<<16) + ((long)j<<8) + i] * inv;
}

__global__ void k_idm(float cst, const float* __restrict__ X, float* __restrict__ Y){
    long idx = (long)blockIdx.x*256 + threadIdx.x;
    if(idx >= 64L*65536) return;
    int j = (int)(idx & 255), i = (int)((idx>>8) & 255);
    Y[idx] = ((i==j)?cst:0.f) - X[idx];
}

// ---------------- residual depthwise conv along sequence (k=33) ----------------
__global__ void k_resconv(const float* __restrict__ qkv, const float* __restrict__ w,
                          float* __restrict__ out){
    long idx = (long)blockIdx.x*256 + threadIdx.x;
    if(idx >= 64L*4352*64) return;
    int dh = (int)(idx & 63); long r = idx >> 6;
    int tok = (int)(r % 4352); long r2 = r / 4352; int hh = (int)(r2 & 7); int b = (int)(r2 >> 3);
    const float* wh = w + hh*33;
    const float* vb = qkv + ((long)b*4352)*1536 + 1024 + hh*64 + dh;
    float s = 0.f;
    #pragma unroll
    for(int j=0;j<33;j++){
        int tv = tok + j - 16;
        if(tv >= 0 && tv < 4352) s += wh[j]*vb[(long)tv*1536];
    }
    out[idx] += s;
}

// ---------------- gather attention heads -> token-major (last 4097 tokens) ----------------
__global__ void k_gather(const float* __restrict__ oat, float* __restrict__ ac){
    long idx = (long)blockIdx.x*256 + threadIdx.x;
    if(idx >= 8L*4097*512) return;
    int c = (int)(idx & 511); long r = idx >> 9; int t = (int)(r % 4097); int b = (int)(r / 4097);
    int hh = c >> 6, dh = c & 63;
    ac[idx] = oat[(((long)(b*8+hh)*4352) + 255 + t)*64 + dh];
}

// ---------------- transposes token<->planar ----------------
__global__ void k_h2planar(const float* __restrict__ h, float* __restrict__ cnn){
    __shared__ float tile[32][33];
    int b = blockIdx.z;
    int c0 = blockIdx.x*32, p0 = blockIdx.y*32;
    int tx = threadIdx.x, ty = threadIdx.y;
    for(int i=ty;i<32;i+=8)
        tile[i][tx] = h[((long)b*4097 + 1 + p0+i)*512 + c0+tx];
    __syncthreads();
    for(int i=ty;i<32;i+=8)
        cnn[((long)b*512 + c0+i)*4096 + p0+tx] = tile[tx][i];
}

__global__ void k_planar2h(const float* __restrict__ yp, float* __restrict__ h2){
    __shared__ float tile[32][33];
    int b = blockIdx.z;
    int c0 = blockIdx.x*32, p0 = blockIdx.y*32;
    int tx = threadIdx.x, ty = threadIdx.y;
    for(int i=ty;i<32;i+=8)
        tile[i][tx] = yp[((long)b*512 + c0+i)*4096 + p0+tx];
    __syncthreads();
    for(int i=ty;i<32;i+=8)
        h2[((long)b*4097 + 1 + p0+i)*512 + c0+tx] = tile[tx][i];
}

__global__ void k_cls_copy(const float* __restrict__ h, float* __restrict__ h2){
    int idx = blockIdx.x*256 + threadIdx.x;
    if(idx >= 8*512) return;
    int b = idx >> 9, c = idx & 511;
    h2[(long)b*4097*512 + c] = h[(long)b*4097*512 + c];
}

// ---------------- fused 7x7 + 5x5 + 3x3 depthwise conv, planar ----------------
__global__ void k_dwconv(const float* __restrict__ cnn,
                         const float* __restrict__ w7, const float* __restrict__ b7,
                         const float* __restrict__ w5, const float* __restrict__ b5,
                         const float* __restrict__ w3, const float* __restrict__ b3,
                         float* __restrict__ yp){
    int bc = blockIdx.x; int c = bc & 511;
    __shared__ float pl[64][65];
    __shared__ float ww[84];
    const float* in = cnn + (long)bc*4096;
    int t = threadIdx.x;
    for(int i=t;i<4096;i+=256) pl[i>>6][i&63] = in[i];
    if(t < 49)      ww[t]      = w7[c*49 + t];
    else if(t < 74) ww[t]      = w5[c*25 + t - 49];
    else if(t < 83) ww[t]      = w3[c*9  + t - 74];
    __syncthreads();
    float bias = b7[c] + b5[c] + b3[c];
    for(int i=t;i<4096;i+=256){
        int y = i >> 6, x = i & 63;
        float s = pl[y][x] + bias;
        #pragma unroll
        for(int ky=0;ky<7;ky++){ int yy=y+ky-3; if((unsigned)yy>=64u) continue;
            #pragma unroll
            for(int kx=0;kx<7;kx++){ int xx=x+kx-3; if((unsigned)xx>=64u) continue;
                s = fmaf(ww[ky*7+kx], pl[yy][xx], s); } }
        #pragma unroll
        for(int ky=0;ky<5;ky++){ int yy=y+ky-2; if((unsigned)yy>=64u) continue;
            #pragma unroll
            for(int kx=0;kx<5;kx++){ int xx=x+kx-2; if((unsigned)xx>=64u) continue;
                s = fmaf(ww[49+ky*5+kx], pl[yy][xx], s); } }
        #pragma unroll
        for(int ky=0;ky<3;ky++){ int yy=y+ky-1; if((unsigned)yy>=64u) continue;
            #pragma unroll
            for(int kx=0;kx<3;kx++){ int xx=x+kx-1; if((unsigned)xx>=64u) continue;
                s = fmaf(ww[74+ky*3+kx], pl[yy][xx], s); } }
        yp[(long)bc*4096 + i] = s;
    }
}

// ---------------- final output: (cls[8,512], feat[8,4096,512]) ----------------
__global__ void k_writeout(const float* __restrict__ h2, float* __restrict__ out){
    long idx = (long)blockIdx.x*256 + threadIdx.x;
    if(idx >= 8L*512 + 8L*4096*512) return;
    if(idx < 8*512){
        int b = (int)(idx >> 9), c = (int)(idx & 511);
        out[idx] = h2[((long)b*4097)*512 + c];
    } else {
        long r = idx - 4096;
        int c = (int)(r & 511); long q = r >> 9; int t = (int)(q % 4096); int b = (int)(q / 4096);
        out[idx] = h2[((long)b*4097 + 1 + t)*512 + c];
    }
}

// ================= host side =================
struct Ptrs {
    float *h,*h2,*xp,*qkv,*ql,*kl,*sim1,*sim3,*a2,*zA,*zB,*xz,*t1,*t2,*a3v,*tmp2,*oat,*ac,*cnn,*yp;
};

static void get_ptrs(Ptrs& p){
    cudaGetSymbolAddress((void**)&p.h,    g_h);
    cudaGetSymbolAddress((void**)&p.h2,   g_h2);
    cudaGetSymbolAddress((void**)&p.xp,   g_xp);
    cudaGetSymbolAddress((void**)&p.qkv,  g_qkv);
    cudaGetSymbolAddress((void**)&p.ql,   g_ql);
    cudaGetSymbolAddress((void**)&p.kl,   g_kl);
    cudaGetSymbolAddress((void**)&p.sim1, g_sim1);
    cudaGetSymbolAddress((void**)&p.sim3, g_sim3);
    cudaGetSymbolAddress((void**)&p.a2,   g_a2);
    cudaGetSymbolAddress((void**)&p.zA,   g_zA);
    cudaGetSymbolAddress((void**)&p.zB,   g_zB);
    cudaGetSymbolAddress((void**)&p.xz,   g_xz);
    cudaGetSymbolAddress((void**)&p.t1,   g_t1);
    cudaGetSymbolAddress((void**)&p.t2,   g_t2);
    cudaGetSymbolAddress((void**)&p.a3v,  g_a3v);
    cudaGetSymbolAddress((void**)&p.tmp2, g_tmp2);
    cudaGetSymbolAddress((void**)&p.oat,  g_oat);
    cudaGetSymbolAddress((void**)&p.ac,   g_ac);
    cudaGetSymbolAddress((void**)&p.cnn,  g_cnn);
    cudaGetSymbolAddress((void**)&p.yp,   g_yp);
}

static void attention(Ptrs& p, float* hbuf,
                      const float* lng, const float* lnb,
                      const float* qkvw, const float* outw, const float* outb,
                      const float* resw)
{
    const long SQKV_B = 4352L*1536;      // batch-b stride in qkv
    const long SQL    = 256L*64;         // per-(b,h) stride in ql/kl
    const long SS1    = 4352L*256;       // per-(b,h) stride sim1
    const long SS3    = 256L*4352;       // per-(b,h) stride sim3
    const long SA2    = 65536L;
    const long SV64   = 256L*64;

    k_zero_pad<<<4080, 256>>>(p.xp);
    k_ln<<<8*4097, 256>>>(hbuf, lng, lnb, p.xp);

    // qkv = xp @ qkv_w^T   (34816 x 1536 x 512)
    k_gemm_nt<<<dim3(544,24,1), 256>>>(p.xp, 512, 0,0, qkvw, 512, 0,0,
                                       p.qkv, 1536, 0,0, 34816, 1536, 512, 1.f, nullptr, 0);

    k_landmarks<<<64*256, 64>>>(p.qkv, p.ql, p.kl);

    // sim1 = (q*scale) @ k_l^T : (4352 x 256 x 64) per (b,h)
    k_gemm_nt<<<dim3(68,4,64), 256>>>(p.qkv, 1536, SQKV_B, 64,
                                      p.kl, 64, 8*SQL, SQL,
                                      p.sim1, 256, 8*SS1, SS1,
                                      4352, 256, 64, 0.125f, nullptr, 0);
    k_softmax<<<64*4352, 256>>>(p.sim1, 256);

    // sim2 = q_l @ k_l^T
    k_gemm_nt<<<dim3(4,4,64), 256>>>(p.ql, 64, 8*SQL, SQL,
                                     p.kl, 64, 8*SQL, SQL,
                                     p.a2, 256, 8*SA2, SA2,
                                     256, 256, 64, 1.f, nullptr, 0);
    k_softmax<<<64*256, 256>>>(p.a2, 256);

    // sim3 = q_l @ k^T : (256 x 4352 x 64)
    k_gemm_nt<<<dim3(4,68,64), 256>>>(p.ql, 64, 8*SQL, SQL,
                                      p.qkv + 512, 1536, SQKV_B, 64,
                                      p.sim3, 4352, 8*SS3, SS3,
                                      256, 4352, 64, 1.f, nullptr, 0);
    k_softmax<<<64*256, 256>>>(p.sim3, 4352);

    // a3v = a3 @ v : (256 x 64 x 4352)
    k_gemm_nn<<<dim3(4,1,64), 256>>>(p.sim3, 4352, 8*SS3, SS3,
                                     p.qkv + 1024, 1536, SQKV_B, 64,
                                     p.a3v, 64, 8*SV64, SV64,
                                     256, 64, 4352, 1.f, 0);

    // ---- Moore-Penrose pinv of a2 (6 iterations) ----
    k_scal_init<<<1, 32>>>();
    k_rowsum_max<<<64*256, 256>>>(p.a2);
    k_colsum_max<<<64, 256>>>(p.a2);
    k_tr_scale<<<16384, 256>>>(p.a2, p.zA);

    float* zc = p.zA; float* zn = p.zB;
    for(int it=0; it<6; it++){
        k_gemm_nn<<<dim3(4,4,64), 256>>>(p.a2, 256, 8*SA2, SA2, zc, 256, 8*SA2, SA2,
                                         p.xz, 256, 8*SA2, SA2, 256,256,256, 1.f, 0);
        k_idm<<<16384, 256>>>(7.f, p.xz, p.t1);
        k_gemm_nn<<<dim3(4,4,64), 256>>>(p.xz, 256, 8*SA2, SA2, p.t1, 256, 8*SA2, SA2,
                                         p.t2, 256, 8*SA2, SA2, 256,256,256, 1.f, 0);
        k_idm<<<16384, 256>>>(15.f, p.t2, p.t1);
        k_gemm_nn<<<dim3(4,4,64), 256>>>(p.xz, 256, 8*SA2, SA2, p.t1, 256, 8*SA2, SA2,
                                         p.t2, 256, 8*SA2, SA2, 256,256,256, 1.f, 0);
        k_idm<<<16384, 256>>>(13.f, p.t2, p.t1);
        k_gemm_nn<<<dim3(4,4,64), 256>>>(zc, 256, 8*SA2, SA2, p.t1, 256, 8*SA2, SA2,
                                         zn, 256, 8*SA2, SA2, 256,256,256, 0.25f, 0);
        float* tmp = zc; zc = zn; zn = tmp;
    }

    // tmp2 = z @ a3v : (256 x 64 x 256)
    k_gemm_nn<<<dim3(4,1,64), 256>>>(zc, 256, 8*SA2, SA2, p.a3v, 64, 8*SV64, SV64,
                                     p.tmp2, 64, 8*SV64, SV64, 256, 64, 256, 1.f, 0);
    // oat = a1 @ tmp2 : (4352 x 64 x 256)
    k_gemm_nn<<<dim3(68,1,64), 256>>>(p.sim1, 256, 8*SS1, SS1, p.tmp2, 64, 8*SV64, SV64,
                                      p.oat, 64, 8L*4352*64, 4352L*64, 4352, 64, 256, 1.f, 0);

    // residual depthwise conv (k=33 along sequence) added to oat
    k_resconv<<<69632, 256>>>(p.qkv, resw, p.oat);

    // heads -> token-major, last 4097 tokens
    k_gather<<<65552, 256>>>(p.oat, p.ac);

    // hbuf += ac @ out_w^T + out_b
    k_gemm_nt<<<dim3(513,8,1), 256>>>(p.ac, 512, 0,0, outw, 512, 0,0,
                                      hbuf, 512, 0,0, 32776, 512, 512, 1.f, outb, 1);
}

extern "C" void kernel_launch(void* const* d_in, const int* in_sizes, int n_in,
                              void* d_out, int out_size)
{
    const float* features = (const float*)d_in[0];
    const float* cls_tok  = (const float*)d_in[1];
    const float* ln1_g    = (const float*)d_in[2];
    const float* ln1_b    = (const float*)d_in[3];
    const float* qkv1_w   = (const float*)d_in[4];
    const float* out1_w   = (const float*)d_in[5];
    const float* out1_b   = (const float*)d_in[6];
    const float* res1_w   = (const float*)d_in[7];
    const float* p7_w     = (const float*)d_in[8];
    const float* p7_b     = (const float*)d_in[9];
    const float* p5_w     = (const float*)d_in[10];
    const float* p5_b     = (const float*)d_in[11];
    const float* p3_w     = (const float*)d_in[12];
    const float* p3_b     = (const float*)d_in[13];
    const float* ln2_g    = (const float*)d_in[14];
    const float* ln2_b    = (const float*)d_in[15];
    const float* qkv2_w   = (const float*)d_in[16];
    const float* out2_w   = (const float*)d_in[17];
    const float* out2_b   = (const float*)d_in[18];
    const float* res2_w   = (const float*)d_in[19];
    float* out = (float*)d_out;

    Ptrs p;
    get_ptrs(p);

    // h0 = [cls; features]  (4096 = 64^2, no extra duplication)
    k_build_h<<<65552, 256>>>(features, cls_tok);

    // block 1: h += nystrom(LN(h))
    attention(p, p.h, ln1_g, ln1_b, qkv1_w, out1_w, out1_b, res1_w);

    // CNN mixer on feature tokens (64x64 grid)
    k_h2planar<<<dim3(16,128,8), dim3(32,8)>>>(p.h, p.cnn);
    k_dwconv<<<4096, 256>>>(p.cnn, p7_w, p7_b, p5_w, p5_b, p3_w, p3_b, p.yp);
    k_planar2h<<<dim3(16,128,8), dim3(32,8)>>>(p.yp, p.h2);
    k_cls_copy<<<16, 256>>>(p.h, p.h2);

    // block 2: h2 += nystrom(LN(h2))
    attention(p, p.h2, ln2_g, ln2_b, qkv2_w, out2_w, out2_b, res2_w);

    // outputs: cls then features
    k_writeout<<<65552, 256>>>(p.h2, out);
}

// round 3
// speedup vs baseline: 1.7611x; 1.7611x over previous
#include <cuda_runtime.h>
#include <math.h>

// ---------------- problem constants ----------------
// B=8, C=512, HEADS=8, DH=64, tokens=4097 (cls+4096), pad=255 -> N=4352
// landmarks m=256, l=17, pinv iters=6, res kernel 33   (rebuild r2b)
#define LSUB 17

// ---------------- device scratch ----------------
__device__ float g_h   [8L*4097*512];
__device__ float g_h2  [8L*4097*512];
__device__ float g_xp  [8L*4352*512];
__device__ float g_qkv [8L*4352*1536];
__device__ float g_ql  [64L*256*64];
__device__ float g_kl  [64L*256*64];
__device__ float g_sim1[64L*4352*256];
__device__ float g_sim3[64L*256*4352];
__device__ float g_a2  [64L*256*256];
__device__ float g_zA  [64L*256*256];
__device__ float g_zB  [64L*256*256];
__device__ float g_xz  [64L*256*256];
__device__ float g_t1  [64L*256*256];
__device__ float g_t2  [64L*256*256];
__device__ float g_a3v [64L*256*64];
__device__ float g_tmp2[64L*256*64];
__device__ float g_oat [64L*4352*64];
__device__ float g_ac  [8L*4097*512];
__device__ float g_cnn [8L*512*4096];
__device__ float g_yp  [8L*512*4096];
__device__ float g_scal[2];

__device__ __forceinline__ float4 ldg4(const float* p){ return *(const float4*)p; }

// ---------------- small kernels ----------------
__global__ void k_build_h(const float* __restrict__ feat, const float* __restrict__ cls){
    long idx = (long)blockIdx.x*256 + threadIdx.x;
    if(idx >= 8L*4097*512) return;
    int c = idx & 511; long r = idx >> 9; int t = (int)(r % 4097); int b = (int)(r / 4097);
    g_h[idx] = (t==0) ? cls[c] : feat[((long)b*4096 + (t-1))*512 + c];
}

__global__ void k_zero_pad(float* __restrict__ xp){
    long idx = (long)blockIdx.x*256 + threadIdx.x;
    if(idx >= 8L*255*512) return;
    int c = idx & 511; long r = idx >> 9; int t = (int)(r % 255); int b = (int)(r / 255);
    xp[((long)b*4352 + t)*512 + c] = 0.f;
}

__global__ void k_ln(const float* __restrict__ h, const float* __restrict__ g,
                     const float* __restrict__ be, float* __restrict__ xp){
    long r = blockIdx.x;                 // b*4097 + t
    int b = (int)(r / 4097); int t = (int)(r % 4097);
    const float* x = h + r*512;
    float* y = xp + ((long)b*4352 + 255 + t)*512;
    int tid = threadIdx.x;
    __shared__ float red[256];
    float s = 0.f;
    for(int i=tid;i<512;i+=256) s += x[i];
    red[tid]=s; __syncthreads();
    for(int k=128;k;k>>=1){ if(tid<k) red[tid]+=red[tid+k]; __syncthreads(); }
    float mean = red[0] * (1.f/512.f); __syncthreads();
    float v = 0.f;
    for(int i=tid;i<512;i+=256){ float d=x[i]-mean; v += d*d; }
    red[tid]=v; __syncthreads();
    for(int k=128;k;k>>=1){ if(tid<k) red[tid]+=red[tid+k]; __syncthreads(); }
    float rstd = rsqrtf(red[0]*(1.f/512.f) + 1e-5f);
    for(int i=tid;i<512;i+=256) y[i] = (x[i]-mean)*rstd*g[i] + be[i];
}

// =====================================================================
// Fast SGEMM family: 128x128 tile, 8x8/thread, BK=8, double-buffered
// =====================================================================

// C = alpha * A @ B^T (+bias)(+C)   A:(M,K) lda, B:(N,K) ldb   batched (b,h)
__global__ void __launch_bounds__(256,2) k_gemm_nt128(
    const float* __restrict__ A, int lda, long sAb, long sAh,
    const float* __restrict__ B, int ldb, long sBb, long sBh,
    float* __restrict__ C, int ldc, long sCb, long sCh,
    int M, int N, int K, float alpha, const float* __restrict__ bias, int acc)
{
    int z = blockIdx.z; int hh = z & 7; int bb = z >> 3;
    A += (long)bb*sAb + (long)hh*sAh;
    B += (long)bb*sBb + (long)hh*sBh;
    C += (long)bb*sCb + (long)hh*sCh;
    __shared__ float As[2][8][132];
    __shared__ float Bs[2][8][132];
    int t = threadIdx.x;
    int tx = t & 15, ty = t >> 4;
    int r0 = blockIdx.x*128, c0 = blockIdx.y*128;
    int lm = t >> 1, lk = (t & 1)*4;
    const float* Ap = A + (long)(r0+lm)*lda + lk;
    const float* Bp = B + (long)(c0+lm)*ldb + lk;
    bool am = (r0+lm) < M;
    bool bn = (c0+lm) < N;
    float4 ar = am ? ldg4(Ap) : make_float4(0.f,0.f,0.f,0.f);
    float4 br = bn ? ldg4(Bp) : make_float4(0.f,0.f,0.f,0.f);
    As[0][lk+0][lm]=ar.x; As[0][lk+1][lm]=ar.y; As[0][lk+2][lm]=ar.z; As[0][lk+3][lm]=ar.w;
    Bs[0][lk+0][lm]=br.x; Bs[0][lk+1][lm]=br.y; Bs[0][lk+2][lm]=br.z; Bs[0][lk+3][lm]=br.w;
    __syncthreads();
    float acc4[8][8];
    #pragma unroll
    for(int i=0;i<8;i++)
        #pragma unroll
        for(int j=0;j<8;j++) acc4[i][j]=0.f;
    int nk = K >> 3;
    int buf = 0;
    for(int kt=0; kt<nk; kt++){
        if(kt+1 < nk){
            ar = am ? ldg4(Ap + (kt+1)*8) : make_float4(0.f,0.f,0.f,0.f);
            br = bn ? ldg4(Bp + (kt+1)*8) : make_float4(0.f,0.f,0.f,0.f);
        }
        #pragma unroll
        for(int kk=0;kk<8;kk++){
            float a[8], b[8];
            *(float4*)(a)   = *(const float4*)&As[buf][kk][ty*4];
            *(float4*)(a+4) = *(const float4*)&As[buf][kk][64+ty*4];
            *(float4*)(b)   = *(const float4*)&Bs[buf][kk][tx*4];
            *(float4*)(b+4) = *(const float4*)&Bs[buf][kk][64+tx*4];
            #pragma unroll
            for(int i=0;i<8;i++)
                #pragma unroll
                for(int j=0;j<8;j++)
                    acc4[i][j] = fmaf(a[i], b[j], acc4[i][j]);
        }
        if(kt+1 < nk){
            buf ^= 1;
            As[buf][lk+0][lm]=ar.x; As[buf][lk+1][lm]=ar.y; As[buf][lk+2][lm]=ar.z; As[buf][lk+3][lm]=ar.w;
            Bs[buf][lk+0][lm]=br.x; Bs[buf][lk+1][lm]=br.y; Bs[buf][lk+2][lm]=br.z; Bs[buf][lk+3][lm]=br.w;
            __syncthreads();
        }
    }
    #pragma unroll
    for(int gi=0; gi<2; gi++)
    #pragma unroll
    for(int i=0;i<4;i++){
        int gm = r0 + gi*64 + ty*4 + i;
        if(gm >= M) continue;
        #pragma unroll
        for(int gj=0; gj<2; gj++){
            int gn = c0 + gj*64 + tx*4;
            float4 v;
            v.x = alpha*acc4[gi*4+i][gj*4+0];
            v.y = alpha*acc4[gi*4+i][gj*4+1];
            v.z = alpha*acc4[gi*4+i][gj*4+2];
            v.w = alpha*acc4[gi*4+i][gj*4+3];
            if(bias){
                float4 bv = ldg4(bias+gn);
                v.x+=bv.x; v.y+=bv.y; v.z+=bv.z; v.w+=bv.w;
            }
            float* cp = C + (long)gm*ldc + gn;
            if(acc){
                float4 ov = *(const float4*)cp;
                v.x+=ov.x; v.y+=ov.y; v.z+=ov.z; v.w+=ov.w;
            }
            *(float4*)cp = v;
        }
    }
}

// C = alpha * A @ B  (NN), optional epilogues for the pinv chain:
//   cmode==1 : C = dconst*I - v
//   D != 0   : D = dconst*I - v   (in addition to C = v)
__global__ void __launch_bounds__(256,2) k_gemm_nn128(
    const float* __restrict__ A, int lda, long sAb, long sAh,
    const float* __restrict__ B, int ldb, long sBb, long sBh,
    float* __restrict__ C, int ldc, long sCb, long sCh,
    float* __restrict__ D, long sDb, long sDh,
    int M, int N, int K, float alpha, float dconst, int cmode)
{
    int z = blockIdx.z; int hh = z & 7; int bb = z >> 3;
    A += (long)bb*sAb + (long)hh*sAh;
    B += (long)bb*sBb + (long)hh*sBh;
    C += (long)bb*sCb + (long)hh*sCh;
    if(D) D += (long)bb*sDb + (long)hh*sDh;
    __shared__ float As[2][8][132];
    __shared__ float Bs[2][8][132];
    int t = threadIdx.x;
    int tx = t & 15, ty = t >> 4;
    int r0 = blockIdx.x*128, c0 = blockIdx.y*128;
    int lm = t >> 1, lk = (t & 1)*4;
    int brow = t >> 5, bcs = t & 31;
    const float* Ap = A + (long)(r0+lm)*lda + lk;
    const float* Bp = B + (long)brow*ldb + c0 + bcs*4;
    bool am = (r0+lm) < M;
    bool bn = (c0+bcs*4) < N;
    float4 ar = am ? ldg4(Ap) : make_float4(0.f,0.f,0.f,0.f);
    float4 br = bn ? ldg4(Bp) : make_float4(0.f,0.f,0.f,0.f);
    As[0][lk+0][lm]=ar.x; As[0][lk+1][lm]=ar.y; As[0][lk+2][lm]=ar.z; As[0][lk+3][lm]=ar.w;
    *(float4*)&Bs[0][brow][bcs*4] = br;
    __syncthreads();
    float acc4[8][8];
    #pragma unroll
    for(int i=0;i<8;i++)
        #pragma unroll
        for(int j=0;j<8;j++) acc4[i][j]=0.f;
    int nk = K >> 3;
    int buf = 0;
    for(int kt=0; kt<nk; kt++){
        if(kt+1 < nk){
            ar = am ? ldg4(Ap + (kt+1)*8) : make_float4(0.f,0.f,0.f,0.f);
            br = bn ? ldg4(Bp + (long)(kt+1)*8*ldb) : make_float4(0.f,0.f,0.f,0.f);
        }
        #pragma unroll
        for(int kk=0;kk<8;kk++){
            float a[8], b[8];
            *(float4*)(a)   = *(const float4*)&As[buf][kk][ty*4];
            *(float4*)(a+4) = *(const float4*)&As[buf][kk][64+ty*4];
            *(float4*)(b)   = *(const float4*)&Bs[buf][kk][tx*4];
            *(float4*)(b+4) = *(const float4*)&Bs[buf][kk][64+tx*4];
            #pragma unroll
            for(int i=0;i<8;i++)
                #pragma unroll
                for(int j=0;j<8;j++)
                    acc4[i][j] = fmaf(a[i], b[j], acc4[i][j]);
        }
        if(kt+1 < nk){
            buf ^= 1;
            As[buf][lk+0][lm]=ar.x; As[buf][lk+1][lm]=ar.y; As[buf][lk+2][lm]=ar.z; As[buf][lk+3][lm]=ar.w;
            *(float4*)&Bs[buf][brow][bcs*4] = br;
            __syncthreads();
        }
    }
    #pragma unroll
    for(int gi=0; gi<2; gi++)
    #pragma unroll
    for(int i=0;i<4;i++){
        int gm = r0 + gi*64 + ty*4 + i;
        if(gm >= M) continue;
        #pragma unroll
        for(int gj=0; gj<2; gj++){
            int gn = c0 + gj*64 + tx*4;
            float4 v;
            v.x = alpha*acc4[gi*4+i][gj*4+0];
            v.y = alpha*acc4[gi*4+i][gj*4+1];
            v.z = alpha*acc4[gi*4+i][gj*4+2];
            v.w = alpha*acc4[gi*4+i][gj*4+3];
            long o = (long)gm*ldc + gn;
            if(D){
                float4 dv;
                dv.x = ((gm==gn+0)?dconst:0.f) - v.x;
                dv.y = ((gm==gn+1)?dconst:0.f) - v.y;
                dv.z = ((gm==gn+2)?dconst:0.f) - v.z;
                dv.w = ((gm==gn+3)?dconst:0.f) - v.w;
                *(float4*)(D+o) = dv;
            }
            if(cmode){
                v.x = ((gm==gn+0)?dconst:0.f) - v.x;
                v.y = ((gm==gn+1)?dconst:0.f) - v.y;
                v.z = ((gm==gn+2)?dconst:0.f) - v.z;
                v.w = ((gm==gn+3)?dconst:0.f) - v.w;
            }
            *(float4*)(C+o) = v;
        }
    }
}

// C = alpha * A @ B  (NN), 128x64 tile, BK=16, 8x4/thread. For N=64 GEMMs.
__global__ void __launch_bounds__(256,2) k_gemm_nn_12864(
    const float* __restrict__ A, int lda, long sAb, long sAh,
    const float* __restrict__ B, int ldb, long sBb, long sBh,
    float* __restrict__ C, int ldc, long sCb, long sCh,
    int M, int N, int K, float alpha)
{
    int z = blockIdx.z; int hh = z & 7; int bb = z >> 3;
    A += (long)bb*sAb + (long)hh*sAh;
    B += (long)bb*sBb + (long)hh*sBh;
    C += (long)bb*sCb + (long)hh*sCh;
    __shared__ float As[2][16][132];
    __shared__ float Bs[2][16][68];
    int t = threadIdx.x;
    int tx = t & 15, ty = t >> 4;
    int r0 = blockIdx.x*128, c0 = blockIdx.y*64;
    int lm0 = t >> 2, lk0 = (t & 3)*4;   // slot t
    int lm1 = lm0 + 64;                  // slot t+256
    int brow = t >> 4, bcs = t & 15;
    const float* Ap0 = A + (long)(r0+lm0)*lda + lk0;
    const float* Ap1 = A + (long)(r0+lm1)*lda + lk0;
    const float* Bp  = B + (long)brow*ldb + c0 + bcs*4;
    bool am0 = (r0+lm0) < M;
    bool am1 = (r0+lm1) < M;
    float4 ar0 = am0 ? ldg4(Ap0) : make_float4(0.f,0.f,0.f,0.f);
    float4 ar1 = am1 ? ldg4(Ap1) : make_float4(0.f,0.f,0.f,0.f);
    float4 br  = ldg4(Bp);
    As[0][lk0+0][lm0]=ar0.x; As[0][lk0+1][lm0]=ar0.y; As[0][lk0+2][lm0]=ar0.z; As[0][lk0+3][lm0]=ar0.w;
    As[0][lk0+0][lm1]=ar1.x; As[0][lk0+1][lm1]=ar1.y; As[0][lk0+2][lm1]=ar1.z; As[0][lk0+3][lm1]=ar1.w;
    *(float4*)&Bs[0][brow][bcs*4] = br;
    __syncthreads();
    float acc4[8][4];
    #pragma unroll
    for(int i=0;i<8;i++)
        #pragma unroll
        for(int j=0;j<4;j++) acc4[i][j]=0.f;
    int nk = K >> 4;
    int buf = 0;
    for(int kt=0; kt<nk; kt++){
        if(kt+1 < nk){
            ar0 = am0 ? ldg4(Ap0 + (kt+1)*16) : make_float4(0.f,0.f,0.f,0.f);
            ar1 = am1 ? ldg4(Ap1 + (kt+1)*16) : make_float4(0.f,0.f,0.f,0.f);
            br  = ldg4(Bp + (long)(kt+1)*16*ldb);
        }
        #pragma unroll
        for(int kk=0;kk<16;kk++){
            float a[8], b[4];
            *(float4*)(a)   = *(const float4*)&As[buf][kk][ty*4];
            *(float4*)(a+4) = *(const float4*)&As[buf][kk][64+ty*4];
            *(float4*)(b)   = *(const float4*)&Bs[buf][kk][tx*4];
            #pragma unroll
            for(int i=0;i<8;i++)
                #pragma unroll
                for(int j=0;j<4;j++)
                    acc4[i][j] = fmaf(a[i], b[j], acc4[i][j]);
        }
        if(kt+1 < nk){
            buf ^= 1;
            As[buf][lk0+0][lm0]=ar0.x; As[buf][lk0+1][lm0]=ar0.y; As[buf][lk0+2][lm0]=ar0.z; As[buf][lk0+3][lm0]=ar0.w;
            As[buf][lk0+0][lm1]=ar1.x; As[buf][lk0+1][lm1]=ar1.y; As[buf][lk0+2][lm1]=ar1.z; As[buf][lk0+3][lm1]=ar1.w;
            *(float4*)&Bs[buf][brow][bcs*4] = br;
            __syncthreads();
        }
    }
    #pragma unroll
    for(int gi=0; gi<2; gi++)
    #pragma unroll
    for(int i=0;i<4;i++){
        int gm = r0 + gi*64 + ty*4 + i;
        if(gm >= M) continue;
        int gn = c0 + tx*4;
        float4 v;
        v.x = alpha*acc4[gi*4+i][0];
        v.y = alpha*acc4[gi*4+i][1];
        v.z = alpha*acc4[gi*4+i][2];
        v.w = alpha*acc4[gi*4+i][3];
        *(float4*)(C + (long)gm*ldc + gn) = v;
    }
}

// ---------------- softmax: warp per row, L=256 ----------------
__global__ void k_softmax256(float* __restrict__ X){
    long row = (long)blockIdx.x*8 + (threadIdx.x>>5);
    int lane = threadIdx.x & 31;
    float* x = X + row*256;
    float v[8]; float mx = -1e30f;
    #pragma unroll
    for(int i=0;i<8;i++){ v[i] = x[i*32+lane]; mx = fmaxf(mx, v[i]); }
    #pragma unroll
    for(int o=16;o;o>>=1) mx = fmaxf(mx, __shfl_xor_sync(0xffffffffu, mx, o));
    float s = 0.f;
    #pragma unroll
    for(int i=0;i<8;i++){ v[i] = __expf(v[i]-mx); s += v[i]; }
    #pragma unroll
    for(int o=16;o;o>>=1) s += __shfl_xor_sync(0xffffffffu, s, o);
    float inv = 1.f/s;
    #pragma unroll
    for(int i=0;i<8;i++) x[i*32+lane] = v[i]*inv;
}

// ---------------- softmax over rows of length L (block version) ----------------
__global__ void k_softmax(float* __restrict__ X, int L){
    long row = blockIdx.x;
    float* x = X + row*(long)L;
    int t = threadIdx.x;
    __shared__ float red[256];
    float mx = -1e30f;
    for(int i=t;i<L;i+=256) mx = fmaxf(mx, x[i]);
    red[t]=mx; __syncthreads();
    for(int k=128;k;k>>=1){ if(t<k) red[t]=fmaxf(red[t],red[t+k]); __syncthreads(); }
    mx = red[0]; __syncthreads();
    float sum = 0.f;
    for(int i=t;i<L;i+=256){ float e=__expf(x[i]-mx); x[i]=e; sum+=e; }
    red[t]=sum; __syncthreads();
    for(int k=128;k;k>>=1){ if(t<k) red[t]+=red[t+k]; __syncthreads(); }
    float inv = 1.f/red[0];
    for(int i=t;i<L;i+=256) x[i] *= inv;
}

// ---------------- landmarks (mean over 17 tokens), q scaled by 1/8 ----------------
__global__ void k_landmarks(const float* __restrict__ qkv, float* __restrict__ ql, float* __restrict__ kl){
    int idx = blockIdx.x;                   // b*8*256 + h*256 + mi
    int mi = idx % 256; int hh = (idx/256) & 7; int b = idx / (256*8);
    int dh = threadIdx.x;
    float sq=0.f, sk=0.f;
    for(int j=0;j<LSUB;j++){
        long tok = (long)mi*LSUB + j;
        const float* base = qkv + ((long)b*4352 + tok)*1536 + hh*64 + dh;
        sq += base[0];
        sk += base[512];
    }
    long o = (long)idx*64 + dh;
    ql[o] = sq * (0.125f/LSUB);
    kl[o] = sk * (1.0f/LSUB);
}

// ---------------- pinv scalar reductions ----------------
__global__ void k_scal_init(){ if(threadIdx.x < 2) g_scal[threadIdx.x] = 0.f; }

__global__ void k_rowsum_max(const float* __restrict__ X){
    long row = blockIdx.x;
    const float* x = X + row*256;
    int t = threadIdx.x;
    __shared__ float red[256];
    red[t] = fabsf(x[t]); __syncthreads();
    for(int k=128;k;k>>=1){ if(t<k) red[t]+=red[t+k]; __syncthreads(); }
    if(t==0) atomicMax((int*)&g_scal[0], __float_as_int(red[0]));
}

__global__ void k_colsum_max(const float* __restrict__ X){
    int b = blockIdx.x; int j = threadIdx.x;
    const float* x = X + (long)b*65536;
    float s = 0.f;
    for(int i=0;i<256;i++) s += fabsf(x[i*256+j]);
    __shared__ float red[256];
    red[j]=s; __syncthreads();
    for(int k=128;k;k>>=1){ if(j<k) red[j]=fmaxf(red[j],red[j+k]); __syncthreads(); }
    if(j==0) atomicMax((int*)&g_scal[1], __float_as_int(red[0]));
}

__global__ void k_tr_scale(const float* __restrict__ X, float* __restrict__ Z){
    long idx = (long)blockIdx.x*256 + threadIdx.x;
    if(idx >= 64L*65536) return;
    float inv = 1.f/(g_scal[0]*g_scal[1]);
    int j = (int)(idx & 255); int i = (int)((idx>>8) & 255); long b = idx >> 16;
    Z[idx] = X[(b<<16) + ((long)j<<8) + i] * inv;
}

// ---------------- residual depthwise conv (k=33 along sequence), smem-tiled ----------------
__global__ void k_resconv2(const float* __restrict__ qkv, const float* __restrict__ w,
                           float* __restrict__ out){
    int bh = blockIdx.y; int hh = bh & 7; int b = bh >> 3;
    int t0 = blockIdx.x*64;
    __shared__ float sv[96][65];
    __shared__ float sw[33];
    int t = threadIdx.x;
    if(t < 33) sw[t] = w[hh*33 + t];
    const float* vb = qkv + ((long)b*4352)*1536 + 1024 + hh*64;
    for(int i=t;i<96*64;i+=256){
        int tok = t0 - 16 + (i>>6); int dh = i&63;
        sv[i>>6][dh] = (tok>=0 && tok<4352) ? vb[(long)tok*1536 + dh] : 0.f;
    }
    __syncthreads();
    for(int i=t;i<64*64;i+=256){
        int lt = i>>6, dh = i&63;
        float s = 0.f;
        #pragma unroll
        for(int j=0;j<33;j++) s = fmaf(sw[j], sv[lt+j][dh], s);
        out[(((long)bh*4352) + t0 + lt)*64 + dh] += s;
    }
}

// ---------------- gather attention heads -> token-major (last 4097 tokens) ----------------
__global__ void k_gather(const float* __restrict__ oat, float* __restrict__ ac){
    long idx = (long)blockIdx.x*256 + threadIdx.x;
    if(idx >= 8L*4097*512) return;
    int c = (int)(idx & 511); long r = idx >> 9; int t = (int)(r % 4097); int b = (int)(r / 4097);
    int hh = c >> 6, dh = c & 63;
    ac[idx] = oat[(((long)(b*8+hh)*4352) + 255 + t)*64 + dh];
}

// ---------------- transposes token<->planar ----------------
__global__ void k_h2planar(const float* __restrict__ h, float* __restrict__ cnn){
    __shared__ float tile[32][33];
    int b = blockIdx.z;
    int c0 = blockIdx.x*32, p0 = blockIdx.y*32;
    int tx = threadIdx.x, ty = threadIdx.y;
    for(int i=ty;i<32;i+=8)
        tile[i][tx] = h[((long)b*4097 + 1 + p0+i)*512 + c0+tx];
    __syncthreads();
    for(int i=ty;i<32;i+=8)
        cnn[((long)b*512 + c0+i)*4096 + p0+tx] = tile[tx][i];
}

__global__ void k_planar2h(const float* __restrict__ yp, float* __restrict__ h2){
    __shared__ float tile[32][33];
    int b = blockIdx.z;
    int c0 = blockIdx.x*32, p0 = blockIdx.y*32;
    int tx = threadIdx.x, ty = threadIdx.y;
    for(int i=ty;i<32;i+=8)
        tile[i][tx] = yp[((long)b*512 + c0+i)*4096 + p0+tx];
    __syncthreads();
    for(int i=ty;i<32;i+=8)
        h2[((long)b*4097 + 1 + p0+i)*512 + c0+tx] = tile[tx][i];
}

__global__ void k_cls_copy(const float* __restrict__ h, float* __restrict__ h2){
    int idx = blockIdx.x*256 + threadIdx.x;
    if(idx >= 8*512) return;
    int b = idx >> 9, c = idx & 511;
    h2[(long)b*4097*512 + c] = h[(long)b*4097*512 + c];
}

// ---------------- fused 7x7 + 5x5 + 3x3 depthwise conv, planar ----------------
__global__ void k_dwconv(const float* __restrict__ cnn,
                         const float* __restrict__ w7, const float* __restrict__ b7,
                         const float* __restrict__ w5, const float* __restrict__ b5,
                         const float* __restrict__ w3, const float* __restrict__ b3,
                         float* __restrict__ yp){
    int bc = blockIdx.x; int c = bc & 511;
    __shared__ float pl[64][65];
    __shared__ float ww[84];
    const float* in = cnn + (long)bc*4096;
    int t = threadIdx.x;
    for(int i=t;i<4096;i+=256) pl[i>>6][i&63] = in[i];
    if(t < 49)      ww[t]      = w7[c*49 + t];
    else if(t < 74) ww[t]      = w5[c*25 + t - 49];
    else if(t < 83) ww[t]      = w3[c*9  + t - 74];
    __syncthreads();
    float bias = b7[c] + b5[c] + b3[c];
    for(int i=t;i<4096;i+=256){
        int y = i >> 6, x = i & 63;
        float s = pl[y][x] + bias;
        #pragma unroll
        for(int ky=0;ky<7;ky++){ int yy=y+ky-3; if((unsigned)yy>=64u) continue;
            #pragma unroll
            for(int kx=0;kx<7;kx++){ int xx=x+kx-3; if((unsigned)xx>=64u) continue;
                s = fmaf(ww[ky*7+kx], pl[yy][xx], s); } }
        #pragma unroll
        for(int ky=0;ky<5;ky++){ int yy=y+ky-2; if((unsigned)yy>=64u) continue;
            #pragma unroll
            for(int kx=0;kx<5;kx++){ int xx=x+kx-2; if((unsigned)xx>=64u) continue;
                s = fmaf(ww[49+ky*5+kx], pl[yy][xx], s); } }
        #pragma unroll
        for(int ky=0;ky<3;ky++){ int yy=y+ky-1; if((unsigned)yy>=64u) continue;
            #pragma unroll
            for(int kx=0;kx<3;kx++){ int xx=x+kx-1; if((unsigned)xx>=64u) continue;
                s = fmaf(ww[74+ky*3+kx], pl[yy][xx], s); } }
        yp[(long)bc*4096 + i] = s;
    }
}

// ---------------- final output: (cls[8,512], feat[8,4096,512]) ----------------
__global__ void k_writeout(const float* __restrict__ h2, float* __restrict__ out){
    long idx = (long)blockIdx.x*256 + threadIdx.x;
    if(idx >= 8L*512 + 8L*4096*512) return;
    if(idx < 8*512){
        int b = (int)(idx >> 9), c = (int)(idx & 511);
        out[idx] = h2[((long)b*4097)*512 + c];
    } else {
        long r = idx - 4096;
        int c = (int)(r & 511); long q = r >> 9; int t = (int)(q % 4096); int b = (int)(q / 4096);
        out[idx] = h2[((long)b*4097 + 1 + t)*512 + c];
    }
}

// ================= host side =================
struct Ptrs {
    float *h,*h2,*xp,*qkv,*ql,*kl,*sim1,*sim3,*a2,*zA,*zB,*xz,*t1,*t2,*a3v,*tmp2,*oat,*ac,*cnn,*yp;
};

static void get_ptrs(Ptrs& p){
    cudaGetSymbolAddress((void**)&p.h,    g_h);
    cudaGetSymbolAddress((void**)&p.h2,   g_h2);
    cudaGetSymbolAddress((void**)&p.xp,   g_xp);
    cudaGetSymbolAddress((void**)&p.qkv,  g_qkv);
    cudaGetSymbolAddress((void**)&p.ql,   g_ql);
    cudaGetSymbolAddress((void**)&p.kl,   g_kl);
    cudaGetSymbolAddress((void**)&p.sim1, g_sim1);
    cudaGetSymbolAddress((void**)&p.sim3, g_sim3);
    cudaGetSymbolAddress((void**)&p.a2,   g_a2);
    cudaGetSymbolAddress((void**)&p.zA,   g_zA);
    cudaGetSymbolAddress((void**)&p.zB,   g_zB);
    cudaGetSymbolAddress((void**)&p.xz,   g_xz);
    cudaGetSymbolAddress((void**)&p.t1,   g_t1);
    cudaGetSymbolAddress((void**)&p.t2,   g_t2);
    cudaGetSymbolAddress((void**)&p.a3v,  g_a3v);
    cudaGetSymbolAddress((void**)&p.tmp2, g_tmp2);
    cudaGetSymbolAddress((void**)&p.oat,  g_oat);
    cudaGetSymbolAddress((void**)&p.ac,   g_ac);
    cudaGetSymbolAddress((void**)&p.cnn,  g_cnn);
    cudaGetSymbolAddress((void**)&p.yp,   g_yp);
}

static void attention(Ptrs& p, float* hbuf,
                      const float* lng, const float* lnb,
                      const float* qkvw, const float* outw, const float* outb,
                      const float* resw)
{
    const long SQKV_B = 4352L*1536;      // batch-b stride in qkv
    const long SQL    = 256L*64;         // per-(b,h) stride in ql/kl
    const long SS1    = 4352L*256;       // per-(b,h) stride sim1
    const long SS3    = 256L*4352;       // per-(b,h) stride sim3
    const long SA2    = 65536L;
    const long SV64   = 256L*64;

    k_zero_pad<<<4080, 256>>>(p.xp);
    k_ln<<<8*4097, 256>>>(hbuf, lng, lnb, p.xp);

    // qkv = xp @ qkv_w^T   (34816 x 1536 x 512)
    k_gemm_nt128<<<dim3(272,12,1), 256>>>(p.xp, 512, 0,0, qkvw, 512, 0,0,
                                          p.qkv, 1536, 0,0, 34816, 1536, 512, 1.f, nullptr, 0);

    k_landmarks<<<64*256, 64>>>(p.qkv, p.ql, p.kl);

    // sim1 = (q*scale) @ k_l^T : (4352 x 256 x 64) per (b,h)
    k_gemm_nt128<<<dim3(34,2,64), 256>>>(p.qkv, 1536, SQKV_B, 64,
                                         p.kl, 64, 8*SQL, SQL,
                                         p.sim1, 256, 8*SS1, SS1,
                                         4352, 256, 64, 0.125f, nullptr, 0);
    k_softmax256<<<64*4352/8, 256>>>(p.sim1);

    // sim2 = q_l @ k_l^T
    k_gemm_nt128<<<dim3(2,2,64), 256>>>(p.ql, 64, 8*SQL, SQL,
                                        p.kl, 64, 8*SQL, SQL,
                                        p.a2, 256, 8*SA2, SA2,
                                        256, 256, 64, 1.f, nullptr, 0);
    k_softmax256<<<64*256/8, 256>>>(p.a2);

    // sim3 = q_l @ k^T : (256 x 4352 x 64)
    k_gemm_nt128<<<dim3(2,34,64), 256>>>(p.ql, 64, 8*SQL, SQL,
                                         p.qkv + 512, 1536, SQKV_B, 64,
                                         p.sim3, 4352, 8*SS3, SS3,
                                         256, 4352, 64, 1.f, nullptr, 0);
    k_softmax<<<64*256, 256>>>(p.sim3, 4352);

    // a3v = a3 @ v : (256 x 64 x 4352)
    k_gemm_nn_12864<<<dim3(2,1,64), 256>>>(p.sim3, 4352, 8*SS3, SS3,
                                           p.qkv + 1024, 1536, SQKV_B, 64,
                                           p.a3v, 64, 8*SV64, SV64,
                                           256, 64, 4352, 1.f);

    // ---- Moore-Penrose pinv of a2 (6 iterations, idm fused in epilogues) ----
    k_scal_init<<<1, 32>>>();
    k_rowsum_max<<<64*256, 256>>>(p.a2);
    k_colsum_max<<<64, 256>>>(p.a2);
    k_tr_scale<<<16384, 256>>>(p.a2, p.zA);

    float* zc = p.zA; float* zn = p.zB;
    for(int it=0; it<6; it++){
        // xz = a2 @ z ; t1 = 7I - xz
        k_gemm_nn128<<<dim3(2,2,64), 256>>>(p.a2, 256, 8*SA2, SA2, zc, 256, 8*SA2, SA2,
                                            p.xz, 256, 8*SA2, SA2, p.t1, 8*SA2, SA2,
                                            256,256,256, 1.f, 7.f, 0);
        // t2 = 15I - xz @ t1
        k_gemm_nn128<<<dim3(2,2,64), 256>>>(p.xz, 256, 8*SA2, SA2, p.t1, 256, 8*SA2, SA2,
                                            p.t2, 256, 8*SA2, SA2, nullptr, 0,0,
                                            256,256,256, 1.f, 15.f, 1);
        // t1 = 13I - xz @ t2
        k_gemm_nn128<<<dim3(2,2,64), 256>>>(p.xz, 256, 8*SA2, SA2, p.t2, 256, 8*SA2, SA2,
                                            p.t1, 256, 8*SA2, SA2, nullptr, 0,0,
                                            256,256,256, 1.f, 13.f, 1);
        // zn = 0.25 * z @ t1
        k_gemm_nn128<<<dim3(2,2,64), 256>>>(zc, 256, 8*SA2, SA2, p.t1, 256, 8*SA2, SA2,
                                            zn, 256, 8*SA2, SA2, nullptr, 0,0,
                                            256,256,256, 0.25f, 0.f, 0);
        float* tmp = zc; zc = zn; zn = tmp;
    }

    // tmp2 = z @ a3v : (256 x 64 x 256)
    k_gemm_nn_12864<<<dim3(2,1,64), 256>>>(zc, 256, 8*SA2, SA2, p.a3v, 64, 8*SV64, SV64,
                                           p.tmp2, 64, 8*SV64, SV64, 256, 64, 256, 1.f);
    // oat = a1 @ tmp2 : (4352 x 64 x 256)
    k_gemm_nn_12864<<<dim3(34,1,64), 256>>>(p.sim1, 256, 8*SS1, SS1, p.tmp2, 64, 8*SV64, SV64,
                                            p.oat, 64, 8L*4352*64, 4352L*64, 4352, 64, 256, 1.f);

    // residual depthwise conv (k=33 along sequence) added to oat
    k_resconv2<<<dim3(68,64), 256>>>(p.qkv, resw, p.oat);

    // heads -> token-major, last 4097 tokens
    k_gather<<<65552, 256>>>(p.oat, p.ac);

    // hbuf += ac @ out_w^T + out_b
    k_gemm_nt128<<<dim3(257,4,1), 256>>>(p.ac, 512, 0,0, outw, 512, 0,0,
                                         hbuf, 512, 0,0, 32776, 512, 512, 1.f, outb, 1);
}

extern "C" void kernel_launch(void* const* d_in, const int* in_sizes, int n_in,
                              void* d_out, int out_size)
{
    const float* features = (const float*)d_in[0];
    const float* cls_tok  = (const float*)d_in[1];
    const float* ln1_g    = (const float*)d_in[2];
    const float* ln1_b    = (const float*)d_in[3];
    const float* qkv1_w   = (const float*)d_in[4];
    const float* out1_w   = (const float*)d_in[5];
    const float* out1_b   = (const float*)d_in[6];
    const float* res1_w   = (const float*)d_in[7];
    const float* p7_w     = (const float*)d_in[8];
    const float* p7_b     = (const float*)d_in[9];
    const float* p5_w     = (const float*)d_in[10];
    const float* p5_b     = (const float*)d_in[11];
    const float* p3_w     = (const float*)d_in[12];
    const float* p3_b     = (const float*)d_in[13];
    const float* ln2_g    = (const float*)d_in[14];
    const float* ln2_b    = (const float*)d_in[15];
    const float* qkv2_w   = (const float*)d_in[16];
    const float* out2_w   = (const float*)d_in[17];
    const float* out2_b   = (const float*)d_in[18];
    const float* res2_w   = (const float*)d_in[19];
    float* out = (float*)d_out;

    Ptrs p;
    get_ptrs(p);

    // h0 = [cls; features]  (4096 = 64^2, no extra duplication)
    k_build_h<<<65552, 256>>>(features, cls_tok);

    // block 1: h += nystrom(LN(h))
    attention(p, p.h, ln1_g, ln1_b, qkv1_w, out1_w, out1_b, res1_w);

    // CNN mixer on feature tokens (64x64 grid)
    k_h2planar<<<dim3(16,128,8), dim3(32,8)>>>(p.h, p.cnn);
    k_dwconv<<<4096, 256>>>(p.cnn, p7_w, p7_b, p5_w, p5_b, p3_w, p3_b, p.yp);
    k_planar2h<<<dim3(16,128,8), dim3(32,8)>>>(p.yp, p.h2);
    k_cls_copy<<<16, 256>>>(p.h, p.h2);

    // block 2: h2 += nystrom(LN(h2))
    attention(p, p.h2, ln2_g, ln2_b, qkv2_w, out2_w, out2_b, res2_w);

    // outputs: cls then features
    k_writeout<<<65552, 256>>>(p.h2, out);
}

// round 5
// speedup vs baseline: 2.8128x; 1.5972x over previous
#include <cuda_runtime.h>
#include <math.h>
#include <stdint.h>

// ---------------- problem constants ----------------
// B=8, C=512, HEADS=8, DH=64, tokens=4097 (cls+4096), pad=255 -> N=4352
// landmarks m=256, l=17, pinv iters=6, res kernel 33   (build r4: tf32 retry)
#define LSUB 17

// ---------------- device scratch ----------------
__device__ float g_h   [8L*4097*512];
__device__ float g_h2  [8L*4097*512];
__device__ float g_xp  [8L*4352*512];
__device__ float g_qkv [8L*4352*1536];
__device__ float g_ql  [64L*256*64];
__device__ float g_kl  [64L*256*64];
__device__ float g_sim1[64L*4352*256];
__device__ float g_sim3[64L*256*4352];
__device__ float g_a2  [64L*256*256];
__device__ float g_zA  [64L*256*256];
__device__ float g_zB  [64L*256*256];
__device__ float g_xz  [64L*256*256];
__device__ float g_t1  [64L*256*256];
__device__ float g_t2  [64L*256*256];
__device__ float g_a3v [64L*256*64];
__device__ float g_tmp2[64L*256*64];
__device__ float g_oat [64L*4352*64];
__device__ float g_ac  [8L*4097*512];
__device__ float g_cnn [8L*512*4096];
__device__ float g_yp  [8L*512*4096];
__device__ float g_scal[2];

__device__ __forceinline__ float4 ldg4(const float* p){ return *(const float4*)p; }

// ---------------- tf32 mma helpers ----------------
__device__ __forceinline__ uint32_t f2tf(float x){
    uint32_t u; asm("cvt.rna.tf32.f32 %0, %1;" : "=r"(u) : "f"(x)); return u;
}
__device__ __forceinline__ uint4 cvt4(float4 v){
    uint4 u; u.x=f2tf(v.x); u.y=f2tf(v.y); u.z=f2tf(v.z); u.w=f2tf(v.w); return u;
}
__device__ __forceinline__ void mma8(float* d, const uint32_t* a, const uint32_t* b){
    asm("mma.sync.aligned.m16n8k8.row.col.f32.tf32.tf32.f32 "
        "{%0,%1,%2,%3}, {%4,%5,%6,%7}, {%8,%9}, {%0,%1,%2,%3};"
        : "+f"(d[0]),"+f"(d[1]),"+f"(d[2]),"+f"(d[3])
        : "r"(a[0]),"r"(a[1]),"r"(a[2]),"r"(a[3]), "r"(b[0]),"r"(b[1]));
}

// ---------------- small kernels ----------------
__global__ void k_build_h(const float* __restrict__ feat, const float* __restrict__ cls){
    long idx = (long)blockIdx.x*256 + threadIdx.x;
    if(idx >= 8L*4097*512) return;
    int c = idx & 511; long r = idx >> 9; int t = (int)(r % 4097); int b = (int)(r / 4097);
    g_h[idx] = (t==0) ? cls[c] : feat[((long)b*4096 + (t-1))*512 + c];
}

__global__ void k_zero_pad(float* __restrict__ xp){
    long idx = (long)blockIdx.x*256 + threadIdx.x;
    if(idx >= 8L*255*512) return;
    int c = idx & 511; long r = idx >> 9; int t = (int)(r % 255); int b = (int)(r / 255);
    xp[((long)b*4352 + t)*512 + c] = 0.f;
}

__global__ void k_ln(const float* __restrict__ h, const float* __restrict__ g,
                     const float* __restrict__ be, float* __restrict__ xp){
    long r = blockIdx.x;                 // b*4097 + t
    int b = (int)(r / 4097); int t = (int)(r % 4097);
    const float* x = h + r*512;
    float* y = xp + ((long)b*4352 + 255 + t)*512;
    int tid = threadIdx.x;
    __shared__ float red[256];
    float s = 0.f;
    for(int i=tid;i<512;i+=256) s += x[i];
    red[tid]=s; __syncthreads();
    for(int k=128;k;k>>=1){ if(tid<k) red[tid]+=red[tid+k]; __syncthreads(); }
    float mean = red[0] * (1.f/512.f); __syncthreads();
    float v = 0.f;
    for(int i=tid;i<512;i+=256){ float d=x[i]-mean; v += d*d; }
    red[tid]=v; __syncthreads();
    for(int k=128;k;k>>=1){ if(tid<k) red[tid]+=red[tid+k]; __syncthreads(); }
    float rstd = rsqrtf(red[0]*(1.f/512.f) + 1e-5f);
    for(int i=tid;i<512;i+=256) y[i] = (x[i]-mean)*rstd*g[i] + be[i];
}

// =====================================================================
// TF32 tensor-core GEMMs: 128x128 block, 8 warps of 64x32, BK=16
// =====================================================================

// C = alpha * A @ B^T (+bias)(+C)   A:(M,K) lda, B:(N,K) ldb   batched (b,h)
__global__ void __launch_bounds__(256,2) k_mma_nt(
    const float* __restrict__ A, int lda, long sAb, long sAh,
    const float* __restrict__ B, int ldb, long sBb, long sBh,
    float* __restrict__ C, int ldc, long sCb, long sCh,
    int M, int N, int K, float alpha, const float* __restrict__ bias, int acc)
{
    int z = blockIdx.z; int hh = z & 7; int bb = z >> 3;
    A += (long)bb*sAb + (long)hh*sAh;
    B += (long)bb*sBb + (long)hh*sBh;
    C += (long)bb*sCb + (long)hh*sCh;
    __shared__ uint32_t As[128][20];
    __shared__ uint32_t Bs[128][20];
    int t = threadIdx.x;
    int lane = t & 31, warp = t >> 5;
    int wm = warp >> 2, wn = warp & 3;        // 2 x 4 warps of 64x32
    int r0 = blockIdx.x*128, c0 = blockIdx.y*128;
    int lrow = t >> 2, lk = (t & 3)*4;
    const float* Ap0 = A + (long)(r0+lrow)*lda + lk;
    const float* Ap1 = A + (long)(r0+lrow+64)*lda + lk;
    const float* Bp0 = B + (long)(c0+lrow)*ldb + lk;
    const float* Bp1 = B + (long)(c0+lrow+64)*ldb + lk;
    bool mA0 = (r0+lrow)<M, mA1 = (r0+lrow+64)<M;
    bool mB0 = (c0+lrow)<N, mB1 = (c0+lrow+64)<N;
    const float4 z4 = make_float4(0.f,0.f,0.f,0.f);
    float4 pa0 = mA0?ldg4(Ap0):z4, pa1 = mA1?ldg4(Ap1):z4;
    float4 pb0 = mB0?ldg4(Bp0):z4, pb1 = mB1?ldg4(Bp1):z4;
    *(uint4*)&As[lrow][lk]    = cvt4(pa0);
    *(uint4*)&As[lrow+64][lk] = cvt4(pa1);
    *(uint4*)&Bs[lrow][lk]    = cvt4(pb0);
    *(uint4*)&Bs[lrow+64][lk] = cvt4(pb1);
    float accr[4][4][4];
    #pragma unroll
    for(int i=0;i<4;i++)
        #pragma unroll
        for(int j=0;j<4;j++)
            #pragma unroll
            for(int q=0;q<4;q++) accr[i][j][q]=0.f;
    int nk = K >> 4;
    for(int kt=0; kt<nk; kt++){
        __syncthreads();
        if(kt+1<nk){
            int o = (kt+1)*16;
            pa0 = mA0?ldg4(Ap0+o):z4; pa1 = mA1?ldg4(Ap1+o):z4;
            pb0 = mB0?ldg4(Bp0+o):z4; pb1 = mB1?ldg4(Bp1+o):z4;
        }
        #pragma unroll
        for(int ks=0;ks<2;ks++){
            int cc = ks*8 + (lane&3);
            uint32_t a[4][4], b[4][2];
            int rA = wm*64 + (lane>>2);
            #pragma unroll
            for(int mt=0;mt<4;mt++){
                a[mt][0]=As[rA+mt*16  ][cc];
                a[mt][1]=As[rA+mt*16+8][cc];
                a[mt][2]=As[rA+mt*16  ][cc+4];
                a[mt][3]=As[rA+mt*16+8][cc+4];
            }
            int rB = wn*32 + (lane>>2);
            #pragma unroll
            for(int nt=0;nt<4;nt++){
                b[nt][0]=Bs[rB+nt*8][cc];
                b[nt][1]=Bs[rB+nt*8][cc+4];
            }
            #pragma unroll
            for(int mt=0;mt<4;mt++)
                #pragma unroll
                for(int nt=0;nt<4;nt++)
                    mma8(accr[mt][nt], a[mt], b[nt]);
        }
        __syncthreads();
        if(kt+1<nk){
            *(uint4*)&As[lrow][lk]    = cvt4(pa0);
            *(uint4*)&As[lrow+64][lk] = cvt4(pa1);
            *(uint4*)&Bs[lrow][lk]    = cvt4(pb0);
            *(uint4*)&Bs[lrow+64][lk] = cvt4(pb1);
        }
    }
    #pragma unroll
    for(int mt=0;mt<4;mt++)
    #pragma unroll
    for(int i=0;i<2;i++){
        int gm = r0 + wm*64 + mt*16 + i*8 + (lane>>2);
        if(gm>=M) continue;
        #pragma unroll
        for(int nt=0;nt<4;nt++){
            int gn = c0 + wn*32 + nt*8 + 2*(lane&3);
            float2 v;
            v.x = alpha*accr[mt][nt][2*i];
            v.y = alpha*accr[mt][nt][2*i+1];
            if(bias){ v.x += bias[gn]; v.y += bias[gn+1]; }
            float* cp = C + (long)gm*ldc + gn;
            if(acc){ v.x += cp[0]; v.y += cp[1]; }
            *(float2*)cp = v;
        }
    }
}

// C = alpha * A @ B  (NN), pinv epilogues:
//   cmode==1 : C = dconst*I - v
//   D != 0   : D = dconst*I - v   (in addition to C = v)
__global__ void __launch_bounds__(256,2) k_mma_nn(
    const float* __restrict__ A, int lda, long sAb, long sAh,
    const float* __restrict__ B, int ldb, long sBb, long sBh,
    float* __restrict__ C, int ldc, long sCb, long sCh,
    float* __restrict__ D, long sDb, long sDh,
    int M, int N, int K, float alpha, float dconst, int cmode)
{
    int z = blockIdx.z; int hh = z & 7; int bb = z >> 3;
    A += (long)bb*sAb + (long)hh*sAh;
    B += (long)bb*sBb + (long)hh*sBh;
    C += (long)bb*sCb + (long)hh*sCh;
    if(D) D += (long)bb*sDb + (long)hh*sDh;
    __shared__ uint32_t As[128][20];
    __shared__ uint32_t Bs[16][136];
    int t = threadIdx.x;
    int lane = t & 31, warp = t >> 5;
    int wm = warp >> 2, wn = warp & 3;
    int r0 = blockIdx.x*128, c0 = blockIdx.y*128;
    int lrow = t >> 2, lk = (t & 3)*4;      // A loader
    int bk = t >> 5, bn = (t & 31)*4;       // B loader: rows bk, bk+8
    const float* Ap0 = A + (long)(r0+lrow)*lda + lk;
    const float* Ap1 = A + (long)(r0+lrow+64)*lda + lk;
    const float* Bq0 = B + (long)bk*ldb + c0 + bn;
    const float* Bq1 = B + (long)(bk+8)*ldb + c0 + bn;
    bool mA0 = (r0+lrow)<M, mA1 = (r0+lrow+64)<M;
    bool mBn = (c0+bn)<N;
    const float4 z4 = make_float4(0.f,0.f,0.f,0.f);
    float4 pa0 = mA0?ldg4(Ap0):z4, pa1 = mA1?ldg4(Ap1):z4;
    float4 pb0 = mBn?ldg4(Bq0):z4, pb1 = mBn?ldg4(Bq1):z4;
    *(uint4*)&As[lrow][lk]    = cvt4(pa0);
    *(uint4*)&As[lrow+64][lk] = cvt4(pa1);
    *(uint4*)&Bs[bk][bn]      = cvt4(pb0);
    *(uint4*)&Bs[bk+8][bn]    = cvt4(pb1);
    float accr[4][4][4];
    #pragma unroll
    for(int i=0;i<4;i++)
        #pragma unroll
        for(int j=0;j<4;j++)
            #pragma unroll
            for(int q=0;q<4;q++) accr[i][j][q]=0.f;
    int nk = K >> 4;
    for(int kt=0; kt<nk; kt++){
        __syncthreads();
        if(kt+1<nk){
            long o = (long)(kt+1)*16;
            pa0 = mA0?ldg4(Ap0+o):z4; pa1 = mA1?ldg4(Ap1+o):z4;
            pb0 = mBn?ldg4(Bq0+o*ldb):z4; pb1 = mBn?ldg4(Bq1+o*ldb):z4;
        }
        #pragma unroll
        for(int ks=0;ks<2;ks++){
            int cc = ks*8 + (lane&3);
            uint32_t a[4][4], b[4][2];
            int rA = wm*64 + (lane>>2);
            #pragma unroll
            for(int mt=0;mt<4;mt++){
                a[mt][0]=As[rA+mt*16  ][cc];
                a[mt][1]=As[rA+mt*16+8][cc];
                a[mt][2]=As[rA+mt*16  ][cc+4];
                a[mt][3]=As[rA+mt*16+8][cc+4];
            }
            int nB = wn*32 + (lane>>2);
            #pragma unroll
            for(int nt=0;nt<4;nt++){
                b[nt][0]=Bs[cc  ][nB+nt*8];
                b[nt][1]=Bs[cc+4][nB+nt*8];
            }
            #pragma unroll
            for(int mt=0;mt<4;mt++)
                #pragma unroll
                for(int nt=0;nt<4;nt++)
                    mma8(accr[mt][nt], a[mt], b[nt]);
        }
        __syncthreads();
        if(kt+1<nk){
            *(uint4*)&As[lrow][lk]    = cvt4(pa0);
            *(uint4*)&As[lrow+64][lk] = cvt4(pa1);
            *(uint4*)&Bs[bk][bn]      = cvt4(pb0);
            *(uint4*)&Bs[bk+8][bn]    = cvt4(pb1);
        }
    }
    #pragma unroll
    for(int mt=0;mt<4;mt++)
    #pragma unroll
    for(int i=0;i<2;i++){
        int gm = r0 + wm*64 + mt*16 + i*8 + (lane>>2);
        if(gm>=M) continue;
        #pragma unroll
        for(int nt=0;nt<4;nt++){
            int gn = c0 + wn*32 + nt*8 + 2*(lane&3);
            float2 v;
            v.x = alpha*accr[mt][nt][2*i];
            v.y = alpha*accr[mt][nt][2*i+1];
            long o = (long)gm*ldc + gn;
            if(D){
                float2 dv;
                dv.x = ((gm==gn  )?dconst:0.f) - v.x;
                dv.y = ((gm==gn+1)?dconst:0.f) - v.y;
                *(float2*)(D+o) = dv;
            }
            if(cmode){
                v.x = ((gm==gn  )?dconst:0.f) - v.x;
                v.y = ((gm==gn+1)?dconst:0.f) - v.y;
            }
            *(float2*)(C+o) = v;
        }
    }
}

// C = alpha * A @ B  (NN fp32), 128x64 tile, BK=16, 8x4/thread. For N=64 GEMMs.
__global__ void __launch_bounds__(256,2) k_gemm_nn_12864(
    const float* __restrict__ A, int lda, long sAb, long sAh,
    const float* __restrict__ B, int ldb, long sBb, long sBh,
    float* __restrict__ C, int ldc, long sCb, long sCh,
    int M, int N, int K, float alpha)
{
    int z = blockIdx.z; int hh = z & 7; int bb = z >> 3;
    A += (long)bb*sAb + (long)hh*sAh;
    B += (long)bb*sBb + (long)hh*sBh;
    C += (long)bb*sCb + (long)hh*sCh;
    __shared__ float As[2][16][132];
    __shared__ float Bs[2][16][68];
    int t = threadIdx.x;
    int tx = t & 15, ty = t >> 4;
    int r0 = blockIdx.x*128, c0 = blockIdx.y*64;
    int lm0 = t >> 2, lk0 = (t & 3)*4;
    int lm1 = lm0 + 64;
    int brow = t >> 4, bcs = t & 15;
    const float* Ap0 = A + (long)(r0+lm0)*lda + lk0;
    const float* Ap1 = A + (long)(r0+lm1)*lda + lk0;
    const float* Bp  = B + (long)brow*ldb + c0 + bcs*4;
    bool am0 = (r0+lm0) < M;
    bool am1 = (r0+lm1) < M;
    float4 ar0 = am0 ? ldg4(Ap0) : make_float4(0.f,0.f,0.f,0.f);
    float4 ar1 = am1 ? ldg4(Ap1) : make_float4(0.f,0.f,0.f,0.f);
    float4 br  = ldg4(Bp);
    As[0][lk0+0][lm0]=ar0.x; As[0][lk0+1][lm0]=ar0.y; As[0][lk0+2][lm0]=ar0.z; As[0][lk0+3][lm0]=ar0.w;
    As[0][lk0+0][lm1]=ar1.x; As[0][lk0+1][lm1]=ar1.y; As[0][lk0+2][lm1]=ar1.z; As[0][lk0+3][lm1]=ar1.w;
    *(float4*)&Bs[0][brow][bcs*4] = br;
    __syncthreads();
    float acc4[8][4];
    #pragma unroll
    for(int i=0;i<8;i++)
        #pragma unroll
        for(int j=0;j<4;j++) acc4[i][j]=0.f;
    int nk = K >> 4;
    int buf = 0;
    for(int kt=0; kt<nk; kt++){
        if(kt+1 < nk){
            ar0 = am0 ? ldg4(Ap0 + (kt+1)*16) : make_float4(0.f,0.f,0.f,0.f);
            ar1 = am1 ? ldg4(Ap1 + (kt+1)*16) : make_float4(0.f,0.f,0.f,0.f);
            br  = ldg4(Bp + (long)(kt+1)*16*ldb);
        }
        #pragma unroll
        for(int kk=0;kk<16;kk++){
            float a[8], b[4];
            *(float4*)(a)   = *(const float4*)&As[buf][kk][ty*4];
            *(float4*)(a+4) = *(const float4*)&As[buf][kk][64+ty*4];
            *(float4*)(b)   = *(const float4*)&Bs[buf][kk][tx*4];
            #pragma unroll
            for(int i=0;i<8;i++)
                #pragma unroll
                for(int j=0;j<4;j++)
                    acc4[i][j] = fmaf(a[i], b[j], acc4[i][j]);
        }
        if(kt+1 < nk){
            buf ^= 1;
            As[buf][lk0+0][lm0]=ar0.x; As[buf][lk0+1][lm0]=ar0.y; As[buf][lk0+2][lm0]=ar0.z; As[buf][lk0+3][lm0]=ar0.w;
            As[buf][lk0+0][lm1]=ar1.x; As[buf][lk0+1][lm1]=ar1.y; As[buf][lk0+2][lm1]=ar1.z; As[buf][lk0+3][lm1]=ar1.w;
            *(float4*)&Bs[buf][brow][bcs*4] = br;
            __syncthreads();
        }
    }
    #pragma unroll
    for(int gi=0; gi<2; gi++)
    #pragma unroll
    for(int i=0;i<4;i++){
        int gm = r0 + gi*64 + ty*4 + i;
        if(gm >= M) continue;
        int gn = c0 + tx*4;
        float4 v;
        v.x = alpha*acc4[gi*4+i][0];
        v.y = alpha*acc4[gi*4+i][1];
        v.z = alpha*acc4[gi*4+i][2];
        v.w = alpha*acc4[gi*4+i][3];
        *(float4*)(C + (long)gm*ldc + gn) = v;
    }
}

// ---------------- softmax: warp per row, L=256 ----------------
__global__ void k_softmax256(float* __restrict__ X){
    long row = (long)blockIdx.x*8 + (threadIdx.x>>5);
    int lane = threadIdx.x & 31;
    float* x = X + row*256;
    float v[8]; float mx = -1e30f;
    #pragma unroll
    for(int i=0;i<8;i++){ v[i] = x[i*32+lane]; mx = fmaxf(mx, v[i]); }
    #pragma unroll
    for(int o=16;o;o>>=1) mx = fmaxf(mx, __shfl_xor_sync(0xffffffffu, mx, o));
    float s = 0.f;
    #pragma unroll
    for(int i=0;i<8;i++){ v[i] = __expf(v[i]-mx); s += v[i]; }
    #pragma unroll
    for(int o=16;o;o>>=1) s += __shfl_xor_sync(0xffffffffu, s, o);
    float inv = 1.f/s;
    #pragma unroll
    for(int i=0;i<8;i++) x[i*32+lane] = v[i]*inv;
}

// ---------------- softmax over rows of length L (block version) ----------------
__global__ void k_softmax(float* __restrict__ X, int L){
    long row = blockIdx.x;
    float* x = X + row*(long)L;
    int t = threadIdx.x;
    __shared__ float red[256];
    float mx = -1e30f;
    for(int i=t;i<L;i+=256) mx = fmaxf(mx, x[i]);
    red[t]=mx; __syncthreads();
    for(int k=128;k;k>>=1){ if(t<k) red[t]=fmaxf(red[t],red[t+k]); __syncthreads(); }
    mx = red[0]; __syncthreads();
    float sum = 0.f;
    for(int i=t;i<L;i+=256){ float e=__expf(x[i]-mx); x[i]=e; sum+=e; }
    red[t]=sum; __syncthreads();
    for(int k=128;k;k>>=1){ if(t<k) red[t]+=red[t+k]; __syncthreads(); }
    float inv = 1.f/red[0];
    for(int i=t;i<L;i+=256) x[i] *= inv;
}

// ---------------- landmarks (mean over 17 tokens), q scaled by 1/8 ----------------
__global__ void k_landmarks(const float* __restrict__ qkv, float* __restrict__ ql, float* __restrict__ kl){
    int idx = blockIdx.x;                   // b*8*256 + h*256 + mi
    int mi = idx % 256; int hh = (idx/256) & 7; int b = idx / (256*8);
    int dh = threadIdx.x;
    float sq=0.f, sk=0.f;
    for(int j=0;j<LSUB;j++){
        long tok = (long)mi*LSUB + j;
        const float* base = qkv + ((long)b*4352 + tok)*1536 + hh*64 + dh;
        sq += base[0];
        sk += base[512];
    }
    long o = (long)idx*64 + dh;
    ql[o] = sq * (0.125f/LSUB);
    kl[o] = sk * (1.0f/LSUB);
}

// ---------------- pinv scalar reductions ----------------
__global__ void k_scal_init(){ if(threadIdx.x < 2) g_scal[threadIdx.x] = 0.f; }

__global__ void k_rowsum_max(const float* __restrict__ X){
    long row = blockIdx.x;
    const float* x = X + row*256;
    int t = threadIdx.x;
    __shared__ float red[256];
    red[t] = fabsf(x[t]); __syncthreads();
    for(int k=128;k;k>>=1){ if(t<k) red[t]+=red[t+k]; __syncthreads(); }
    if(t==0) atomicMax((int*)&g_scal[0], __float_as_int(red[0]));
}

__global__ void k_colsum_max(const float* __restrict__ X){
    int b = blockIdx.x; int j = threadIdx.x;
    const float* x = X + (long)b*65536;
    float s = 0.f;
    for(int i=0;i<256;i++) s += fabsf(x[i*256+j]);
    __shared__ float red[256];
    red[j]=s; __syncthreads();
    for(int k=128;k;k>>=1){ if(j<k) red[j]=fmaxf(red[j],red[j+k]); __syncthreads(); }
    if(j==0) atomicMax((int*)&g_scal[1], __float_as_int(red[0]));
}

__global__ void k_tr_scale(const float* __restrict__ X, float* __restrict__ Z){
    long idx = (long)blockIdx.x*256 + threadIdx.x;
    if(idx >= 64L*65536) return;
    float inv = 1.f/(g_scal[0]*g_scal[1]);
    int j = (int)(idx & 255); int i = (int)((idx>>8) & 255); long b = idx >> 16;
    Z[idx] = X[(b<<16) + ((long)j<<8) + i] * inv;
}

// ---------------- residual depthwise conv (k=33 along sequence), smem-tiled ----------------
__global__ void k_resconv2(const float* __restrict__ qkv, const float* __restrict__ w,
                           float* __restrict__ out){
    int bh = blockIdx.y; int hh = bh & 7; int b = bh >> 3;
    int t0 = blockIdx.x*64;
    __shared__ float sv[96][65];
    __shared__ float sw[33];
    int t = threadIdx.x;
    if(t < 33) sw[t] = w[hh*33 + t];
    const float* vb = qkv + ((long)b*4352)*1536 + 1024 + hh*64;
    for(int i=t;i<96*64;i+=256){
        int tok = t0 - 16 + (i>>6); int dh = i&63;
        sv[i>>6][dh] = (tok>=0 && tok<4352) ? vb[(long)tok*1536 + dh] : 0.f;
    }
    __syncthreads();
    for(int i=t;i<64*64;i+=256){
        int lt = i>>6, dh = i&63;
        float s = 0.f;
        #pragma unroll
        for(int j=0;j<33;j++) s = fmaf(sw[j], sv[lt+j][dh], s);
        out[(((long)bh*4352) + t0 + lt)*64 + dh] += s;
    }
}

// ---------------- gather attention heads -> token-major (last 4097 tokens) ----------------
__global__ void k_gather(const float* __restrict__ oat, float* __restrict__ ac){
    long idx = (long)blockIdx.x*256 + threadIdx.x;
    if(idx >= 8L*4097*512) return;
    int c = (int)(idx & 511); long r = idx >> 9; int t = (int)(r % 4097); int b = (int)(r / 4097);
    int hh = c >> 6, dh = c & 63;
    ac[idx] = oat[(((long)(b*8+hh)*4352) + 255 + t)*64 + dh];
}

// ---------------- transposes token<->planar ----------------
__global__ void k_h2planar(const float* __restrict__ h, float* __restrict__ cnn){
    __shared__ float tile[32][33];
    int b = blockIdx.z;
    int c0 = blockIdx.x*32, p0 = blockIdx.y*32;
    int tx = threadIdx.x, ty = threadIdx.y;
    for(int i=ty;i<32;i+=8)
        tile[i][tx] = h[((long)b*4097 + 1 + p0+i)*512 + c0+tx];
    __syncthreads();
    for(int i=ty;i<32;i+=8)
        cnn[((long)b*512 + c0+i)*4096 + p0+tx] = tile[tx][i];
}

__global__ void k_planar2h(const float* __restrict__ yp, float* __restrict__ h2){
    __shared__ float tile[32][33];
    int b = blockIdx.z;
    int c0 = blockIdx.x*32, p0 = blockIdx.y*32;
    int tx = threadIdx.x, ty = threadIdx.y;
    for(int i=ty;i<32;i+=8)
        tile[i][tx] = yp[((long)b*512 + c0+i)*4096 + p0+tx];
    __syncthreads();
    for(int i=ty;i<32;i+=8)
        h2[((long)b*4097 + 1 + p0+i)*512 + c0+tx] = tile[tx][i];
}

__global__ void k_cls_copy(const float* __restrict__ h, float* __restrict__ h2){
    int idx = blockIdx.x*256 + threadIdx.x;
    if(idx >= 8*512) return;
    int b = idx >> 9, c = idx & 511;
    h2[(long)b*4097*512 + c] = h[(long)b*4097*512 + c];
}

// ---------------- fused 7x7 + 5x5 + 3x3 depthwise conv, planar ----------------
__global__ void k_dwconv(const float* __restrict__ cnn,
                         const float* __restrict__ w7, const float* __restrict__ b7,
                         const float* __restrict__ w5, const float* __restrict__ b5,
                         const float* __restrict__ w3, const float* __restrict__ b3,
                         float* __restrict__ yp){
    int bc = blockIdx.x; int c = bc & 511;
    __shared__ float pl[64][65];
    __shared__ float ww[84];
    const float* in = cnn + (long)bc*4096;
    int t = threadIdx.x;
    for(int i=t;i<4096;i+=256) pl[i>>6][i&63] = in[i];
    if(t < 49)      ww[t]      = w7[c*49 + t];
    else if(t < 74) ww[t]      = w5[c*25 + t - 49];
    else if(t < 83) ww[t]      = w3[c*9  + t - 74];
    __syncthreads();
    float bias = b7[c] + b5[c] + b3[c];
    for(int i=t;i<4096;i+=256){
        int y = i >> 6, x = i & 63;
        float s = pl[y][x] + bias;
        #pragma unroll
        for(int ky=0;ky<7;ky++){ int yy=y+ky-3; if((unsigned)yy>=64u) continue;
            #pragma unroll
            for(int kx=0;kx<7;kx++){ int xx=x+kx-3; if((unsigned)xx>=64u) continue;
                s = fmaf(ww[ky*7+kx], pl[yy][xx], s); } }
        #pragma unroll
        for(int ky=0;ky<5;ky++){ int yy=y+ky-2; if((unsigned)yy>=64u) continue;
            #pragma unroll
            for(int kx=0;kx<5;kx++){ int xx=x+kx-2; if((unsigned)xx>=64u) continue;
                s = fmaf(ww[49+ky*5+kx], pl[yy][xx], s); } }
        #pragma unroll
        for(int ky=0;ky<3;ky++){ int yy=y+ky-1; if((unsigned)yy>=64u) continue;
            #pragma unroll
            for(int kx=0;kx<3;kx++){ int xx=x+kx-1; if((unsigned)xx>=64u) continue;
                s = fmaf(ww[74+ky*3+kx], pl[yy][xx], s); } }
        yp[(long)bc*4096 + i] = s;
    }
}

// ---------------- final output: (cls[8,512], feat[8,4096,512]) ----------------
__global__ void k_writeout(const float* __restrict__ h2, float* __restrict__ out){
    long idx = (long)blockIdx.x*256 + threadIdx.x;
    if(idx >= 8L*512 + 8L*4096*512) return;
    if(idx < 8*512){
        int b = (int)(idx >> 9), c = (int)(idx & 511);
        out[idx] = h2[((long)b*4097)*512 + c];
    } else {
        long r = idx - 4096;
        int c = (int)(r & 511); long q = r >> 9; int t = (int)(q % 4096); int b = (int)(q / 4096);
        out[idx] = h2[((long)b*4097 + 1 + t)*512 + c];
    }
}

// ================= host side =================
struct Ptrs {
    float *h,*h2,*xp,*qkv,*ql,*kl,*sim1,*sim3,*a2,*zA,*zB,*xz,*t1,*t2,*a3v,*tmp2,*oat,*ac,*cnn,*yp;
};

static void get_ptrs(Ptrs& p){
    cudaGetSymbolAddress((void**)&p.h,    g_h);
    cudaGetSymbolAddress((void**)&p.h2,   g_h2);
    cudaGetSymbolAddress((void**)&p.xp,   g_xp);
    cudaGetSymbolAddress((void**)&p.qkv,  g_qkv);
    cudaGetSymbolAddress((void**)&p.ql,   g_ql);
    cudaGetSymbolAddress((void**)&p.kl,   g_kl);
    cudaGetSymbolAddress((void**)&p.sim1, g_sim1);
    cudaGetSymbolAddress((void**)&p.sim3, g_sim3);
    cudaGetSymbolAddress((void**)&p.a2,   g_a2);
    cudaGetSymbolAddress((void**)&p.zA,   g_zA);
    cudaGetSymbolAddress((void**)&p.zB,   g_zB);
    cudaGetSymbolAddress((void**)&p.xz,   g_xz);
    cudaGetSymbolAddress((void**)&p.t1,   g_t1);
    cudaGetSymbolAddress((void**)&p.t2,   g_t2);
    cudaGetSymbolAddress((void**)&p.a3v,  g_a3v);
    cudaGetSymbolAddress((void**)&p.tmp2, g_tmp2);
    cudaGetSymbolAddress((void**)&p.oat,  g_oat);
    cudaGetSymbolAddress((void**)&p.ac,   g_ac);
    cudaGetSymbolAddress((void**)&p.cnn,  g_cnn);
    cudaGetSymbolAddress((void**)&p.yp,   g_yp);
}

static void attention(Ptrs& p, float* hbuf,
                      const float* lng, const float* lnb,
                      const float* qkvw, const float* outw, const float* outb,
                      const float* resw)
{
    const long SQKV_B = 4352L*1536;      // batch-b stride in qkv
    const long SQL    = 256L*64;         // per-(b,h) stride in ql/kl
    const long SS1    = 4352L*256;       // per-(b,h) stride sim1
    const long SS3    = 256L*4352;       // per-(b,h) stride sim3
    const long SA2    = 65536L;
    const long SV64   = 256L*64;

    k_zero_pad<<<4080, 256>>>(p.xp);
    k_ln<<<8*4097, 256>>>(hbuf, lng, lnb, p.xp);

    // qkv = xp @ qkv_w^T   (34816 x 1536 x 512)
    k_mma_nt<<<dim3(272,12,1), 256>>>(p.xp, 512, 0,0, qkvw, 512, 0,0,
                                      p.qkv, 1536, 0,0, 34816, 1536, 512, 1.f, nullptr, 0);

    k_landmarks<<<64*256, 64>>>(p.qkv, p.ql, p.kl);

    // sim1 = (q*scale) @ k_l^T : (4352 x 256 x 64) per (b,h)
    k_mma_nt<<<dim3(34,2,64), 256>>>(p.qkv, 1536, SQKV_B, 64,
                                     p.kl, 64, 8*SQL, SQL,
                                     p.sim1, 256, 8*SS1, SS1,
                                     4352, 256, 64, 0.125f, nullptr, 0);
    k_softmax256<<<64*4352/8, 256>>>(p.sim1);

    // sim2 = q_l @ k_l^T
    k_mma_nt<<<dim3(2,2,64), 256>>>(p.ql, 64, 8*SQL, SQL,
                                    p.kl, 64, 8*SQL, SQL,
                                    p.a2, 256, 8*SA2, SA2,
                                    256, 256, 64, 1.f, nullptr, 0);
    k_softmax256<<<64*256/8, 256>>>(p.a2);

    // sim3 = q_l @ k^T : (256 x 4352 x 64)
    k_mma_nt<<<dim3(2,34,64), 256>>>(p.ql, 64, 8*SQL, SQL,
                                     p.qkv + 512, 1536, SQKV_B, 64,
                                     p.sim3, 4352, 8*SS3, SS3,
                                     256, 4352, 64, 1.f, nullptr, 0);
    k_softmax<<<64*256, 256>>>(p.sim3, 4352);

    // a3v = a3 @ v : (256 x 64 x 4352)
    k_gemm_nn_12864<<<dim3(2,1,64), 256>>>(p.sim3, 4352, 8*SS3, SS3,
                                           p.qkv + 1024, 1536, SQKV_B, 64,
                                           p.a3v, 64, 8*SV64, SV64,
                                           256, 64, 4352, 1.f);

    // ---- Moore-Penrose pinv of a2 (6 iterations, idm fused in epilogues) ----
    k_scal_init<<<1, 32>>>();
    k_rowsum_max<<<64*256, 256>>>(p.a2);
    k_colsum_max<<<64, 256>>>(p.a2);
    k_tr_scale<<<16384, 256>>>(p.a2, p.zA);

    float* zc = p.zA; float* zn = p.zB;
    for(int it=0; it<6; it++){
        // xz = a2 @ z ; t1 = 7I - xz
        k_mma_nn<<<dim3(2,2,64), 256>>>(p.a2, 256, 8*SA2, SA2, zc, 256, 8*SA2, SA2,
                                        p.xz, 256, 8*SA2, SA2, p.t1, 8*SA2, SA2,
                                        256,256,256, 1.f, 7.f, 0);
        // t2 = 15I - xz @ t1
        k_mma_nn<<<dim3(2,2,64), 256>>>(p.xz, 256, 8*SA2, SA2, p.t1, 256, 8*SA2, SA2,
                                        p.t2, 256, 8*SA2, SA2, nullptr, 0,0,
                                        256,256,256, 1.f, 15.f, 1);
        // t1 = 13I - xz @ t2
        k_mma_nn<<<dim3(2,2,64), 256>>>(p.xz, 256, 8*SA2, SA2, p.t2, 256, 8*SA2, SA2,
                                        p.t1, 256, 8*SA2, SA2, nullptr, 0,0,
                                        256,256,256, 1.f, 13.f, 1);
        // zn = 0.25 * z @ t1
        k_mma_nn<<<dim3(2,2,64), 256>>>(zc, 256, 8*SA2, SA2, p.t1, 256, 8*SA2, SA2,
                                        zn, 256, 8*SA2, SA2, nullptr, 0,0,
                                        256,256,256, 0.25f, 0.f, 0);
        float* tmp = zc; zc = zn; zn = tmp;
    }

    // tmp2 = z @ a3v : (256 x 64 x 256)
    k_gemm_nn_12864<<<dim3(2,1,64), 256>>>(zc, 256, 8*SA2, SA2, p.a3v, 64, 8*SV64, SV64,
                                           p.tmp2, 64, 8*SV64, SV64, 256, 64, 256, 1.f);
    // oat = a1 @ tmp2 : (4352 x 64 x 256)
    k_gemm_nn_12864<<<dim3(34,1,64), 256>>>(p.sim1, 256, 8*SS1, SS1, p.tmp2, 64, 8*SV64, SV64,
                                            p.oat, 64, 8L*4352*64, 4352L*64, 4352, 64, 256, 1.f);

    // residual depthwise conv (k=33 along sequence) added to oat
    k_resconv2<<<dim3(68,64), 256>>>(p.qkv, resw, p.oat);

    // heads -> token-major, last 4097 tokens
    k_gather<<<65552, 256>>>(p.oat, p.ac);

    // hbuf += ac @ out_w^T + out_b
    k_mma_nt<<<dim3(257,4,1), 256>>>(p.ac, 512, 0,0, outw, 512, 0,0,
                                     hbuf, 512, 0,0, 32776, 512, 512, 1.f, outb, 1);
}

extern "C" void kernel_launch(void* const* d_in, const int* in_sizes, int n_in,
                              void* d_out, int out_size)
{
    const float* features = (const float*)d_in[0];
    const float* cls_tok  = (const float*)d_in[1];
    const float* ln1_g    = (const float*)d_in[2];
    const float* ln1_b    = (const float*)d_in[3];
    const float* qkv1_w   = (const float*)d_in[4];
    const float* out1_w   = (const float*)d_in[5];
    const float* out1_b   = (const float*)d_in[6];
    const float* res1_w   = (const float*)d_in[7];
    const float* p7_w     = (const float*)d_in[8];
    const float* p7_b     = (const float*)d_in[9];
    const float* p5_w     = (const float*)d_in[10];
    const float* p5_b     = (const float*)d_in[11];
    const float* p3_w     = (const float*)d_in[12];
    const float* p3_b     = (const float*)d_in[13];
    const float* ln2_g    = (const float*)d_in[14];
    const float* ln2_b    = (const float*)d_in[15];
    const float* qkv2_w   = (const float*)d_in[16];
    const float* out2_w   = (const float*)d_in[17];
    const float* out2_b   = (const float*)d_in[18];
    const float* res2_w   = (const float*)d_in[19];
    float* out = (float*)d_out;

    Ptrs p;
    get_ptrs(p);

    // h0 = [cls; features]  (4096 = 64^2, no extra duplication)
    k_build_h<<<65552, 256>>>(features, cls_tok);

    // block 1: h += nystrom(LN(h))
    attention(p, p.h, ln1_g, ln1_b, qkv1_w, out1_w, out1_b, res1_w);

    // CNN mixer on feature tokens (64x64 grid)
    k_h2planar<<<dim3(16,128,8), dim3(32,8)>>>(p.h, p.cnn);
    k_dwconv<<<4096, 256>>>(p.cnn, p7_w, p7_b, p5_w, p5_b, p3_w, p3_b, p.yp);
    k_planar2h<<<dim3(16,128,8), dim3(32,8)>>>(p.yp, p.h2);
    k_cls_copy<<<16, 256>>>(p.h, p.h2);

    // block 2: h2 += nystrom(LN(h2))
    attention(p, p.h2, ln2_g, ln2_b, qkv2_w, out2_w, out2_b, res2_w);

    // outputs: cls then features
    k_writeout<<<65552, 256>>>(p.h2, out);
}

// round 6
// speedup vs baseline: 2.9532x; 1.0499x over previous
#include <cuda_runtime.h>
#include <math.h>
#include <stdint.h>

// ---------------- problem constants ----------------
// B=8, C=512, HEADS=8, DH=64, tokens=4097 (cls+4096), pad=255 -> N=4352
// landmarks m=256, l=17, pinv iters=6, res kernel 33   (build r6: fused softmax + direct-write)
#define LSUB 17

// ---------------- device scratch ----------------
__device__ float g_h   [8L*4097*512];
__device__ float g_h2  [8L*4097*512];
__device__ float g_xp  [8L*4352*512];
__device__ float g_qkv [8L*4352*1536];
__device__ float g_ql  [64L*256*64];
__device__ float g_kl  [64L*256*64];
__device__ float g_sim1[64L*4352*256];
__device__ float g_sim3[64L*256*4352];
__device__ float g_a2  [64L*256*256];
__device__ float g_zA  [64L*256*256];
__device__ float g_zB  [64L*256*256];
__device__ float g_xz  [64L*256*256];
__device__ float g_t1  [64L*256*256];
__device__ float g_t2  [64L*256*256];
__device__ float g_a3v [64L*256*64];
__device__ float g_tmp2[64L*256*64];
__device__ float g_ac  [8L*4097*512];
__device__ float g_cnn [8L*512*4096];
__device__ float g_yp  [8L*512*4096];
__device__ float g_scal[2];

__device__ __forceinline__ float4 ldg4(const float* p){ return *(const float4*)p; }

// ---------------- tf32 mma helpers ----------------
__device__ __forceinline__ uint32_t f2tf(float x){
    uint32_t u; asm("cvt.rna.tf32.f32 %0, %1;" : "=r"(u) : "f"(x)); return u;
}
__device__ __forceinline__ uint4 cvt4(float4 v){
    uint4 u; u.x=f2tf(v.x); u.y=f2tf(v.y); u.z=f2tf(v.z); u.w=f2tf(v.w); return u;
}
__device__ __forceinline__ void mma8(float* d, const uint32_t* a, const uint32_t* b){
    asm("mma.sync.aligned.m16n8k8.row.col.f32.tf32.tf32.f32 "
        "{%0,%1,%2,%3}, {%4,%5,%6,%7}, {%8,%9}, {%0,%1,%2,%3};"
        : "+f"(d[0]),"+f"(d[1]),"+f"(d[2]),"+f"(d[3])
        : "r"(a[0]),"r"(a[1]),"r"(a[2]),"r"(a[3]), "r"(b[0]),"r"(b[1]));
}

// ---------------- small kernels ----------------
__global__ void k_build_h(const float* __restrict__ feat, const float* __restrict__ cls){
    long idx = (long)blockIdx.x*256 + threadIdx.x;
    if(idx >= 8L*4097*512) return;
    int c = idx & 511; long r = idx >> 9; int t = (int)(r % 4097); int b = (int)(r / 4097);
    g_h[idx] = (t==0) ? cls[c] : feat[((long)b*4096 + (t-1))*512 + c];
}

__global__ void k_zero_pad(float* __restrict__ xp){
    long idx = (long)blockIdx.x*256 + threadIdx.x;
    if(idx >= 8L*255*512) return;
    int c = idx & 511; long r = idx >> 9; int t = (int)(r % 255); int b = (int)(r / 255);
    xp[((long)b*4352 + t)*512 + c] = 0.f;
}

__global__ void k_ln(const float* __restrict__ h, const float* __restrict__ g,
                     const float* __restrict__ be, float* __restrict__ xp){
    long r = blockIdx.x;                 // b*4097 + t
    int b = (int)(r / 4097); int t = (int)(r % 4097);
    const float* x = h + r*512;
    float* y = xp + ((long)b*4352 + 255 + t)*512;
    int tid = threadIdx.x;
    __shared__ float red[256];
    float s = 0.f;
    for(int i=tid;i<512;i+=256) s += x[i];
    red[tid]=s; __syncthreads();
    for(int k=128;k;k>>=1){ if(tid<k) red[tid]+=red[tid+k]; __syncthreads(); }
    float mean = red[0] * (1.f/512.f); __syncthreads();
    float v = 0.f;
    for(int i=tid;i<512;i+=256){ float d=x[i]-mean; v += d*d; }
    red[tid]=v; __syncthreads();
    for(int k=128;k;k>>=1){ if(tid<k) red[tid]+=red[tid+k]; __syncthreads(); }
    float rstd = rsqrtf(red[0]*(1.f/512.f) + 1e-5f);
    for(int i=tid;i<512;i+=256) y[i] = (x[i]-mean)*rstd*g[i] + be[i];
}

// =====================================================================
// TF32 tensor-core GEMMs: 128x128 block, 8 warps of 64x32, BK=16
// =====================================================================

// C = alpha * A @ B^T (+bias)(+C)   A:(M,K) lda, B:(N,K) ldb   batched (b,h)
__global__ void __launch_bounds__(256,2) k_mma_nt(
    const float* __restrict__ A, int lda, long sAb, long sAh,
    const float* __restrict__ B, int ldb, long sBb, long sBh,
    float* __restrict__ C, int ldc, long sCb, long sCh,
    int M, int N, int K, float alpha, const float* __restrict__ bias, int acc)
{
    int z = blockIdx.z; int hh = z & 7; int bb = z >> 3;
    A += (long)bb*sAb + (long)hh*sAh;
    B += (long)bb*sBb + (long)hh*sBh;
    C += (long)bb*sCb + (long)hh*sCh;
    __shared__ uint32_t As[128][20];
    __shared__ uint32_t Bs[128][20];
    int t = threadIdx.x;
    int lane = t & 31, warp = t >> 5;
    int wm = warp >> 2, wn = warp & 3;        // 2 x 4 warps of 64x32
    int r0 = blockIdx.x*128, c0 = blockIdx.y*128;
    int lrow = t >> 2, lk = (t & 3)*4;
    const float* Ap0 = A + (long)(r0+lrow)*lda + lk;
    const float* Ap1 = A + (long)(r0+lrow+64)*lda + lk;
    const float* Bp0 = B + (long)(c0+lrow)*ldb + lk;
    const float* Bp1 = B + (long)(c0+lrow+64)*ldb + lk;
    bool mA0 = (r0+lrow)<M, mA1 = (r0+lrow+64)<M;
    bool mB0 = (c0+lrow)<N, mB1 = (c0+lrow+64)<N;
    const float4 z4 = make_float4(0.f,0.f,0.f,0.f);
    float4 pa0 = mA0?ldg4(Ap0):z4, pa1 = mA1?ldg4(Ap1):z4;
    float4 pb0 = mB0?ldg4(Bp0):z4, pb1 = mB1?ldg4(Bp1):z4;
    *(uint4*)&As[lrow][lk]    = cvt4(pa0);
    *(uint4*)&As[lrow+64][lk] = cvt4(pa1);
    *(uint4*)&Bs[lrow][lk]    = cvt4(pb0);
    *(uint4*)&Bs[lrow+64][lk] = cvt4(pb1);
    float accr[4][4][4];
    #pragma unroll
    for(int i=0;i<4;i++)
        #pragma unroll
        for(int j=0;j<4;j++)
            #pragma unroll
            for(int q=0;q<4;q++) accr[i][j][q]=0.f;
    int nk = K >> 4;
    for(int kt=0; kt<nk; kt++){
        __syncthreads();
        if(kt+1<nk){
            int o = (kt+1)*16;
            pa0 = mA0?ldg4(Ap0+o):z4; pa1 = mA1?ldg4(Ap1+o):z4;
            pb0 = mB0?ldg4(Bp0+o):z4; pb1 = mB1?ldg4(Bp1+o):z4;
        }
        #pragma unroll
        for(int ks=0;ks<2;ks++){
            int cc = ks*8 + (lane&3);
            uint32_t a[4][4], b[4][2];
            int rA = wm*64 + (lane>>2);
            #pragma unroll
            for(int mt=0;mt<4;mt++){
                a[mt][0]=As[rA+mt*16  ][cc];
                a[mt][1]=As[rA+mt*16+8][cc];
                a[mt][2]=As[rA+mt*16  ][cc+4];
                a[mt][3]=As[rA+mt*16+8][cc+4];
            }
            int rB = wn*32 + (lane>>2);
            #pragma unroll
            for(int nt=0;nt<4;nt++){
                b[nt][0]=Bs[rB+nt*8][cc];
                b[nt][1]=Bs[rB+nt*8][cc+4];
            }
            #pragma unroll
            for(int mt=0;mt<4;mt++)
                #pragma unroll
                for(int nt=0;nt<4;nt++)
                    mma8(accr[mt][nt], a[mt], b[nt]);
        }
        __syncthreads();
        if(kt+1<nk){
            *(uint4*)&As[lrow][lk]    = cvt4(pa0);
            *(uint4*)&As[lrow+64][lk] = cvt4(pa1);
            *(uint4*)&Bs[lrow][lk]    = cvt4(pb0);
            *(uint4*)&Bs[lrow+64][lk] = cvt4(pb1);
        }
    }
    #pragma unroll
    for(int mt=0;mt<4;mt++)
    #pragma unroll
    for(int i=0;i<2;i++){
        int gm = r0 + wm*64 + mt*16 + i*8 + (lane>>2);
        if(gm>=M) continue;
        #pragma unroll
        for(int nt=0;nt<4;nt++){
            int gn = c0 + wn*32 + nt*8 + 2*(lane&3);
            float2 v;
            v.x = alpha*accr[mt][nt][2*i];
            v.y = alpha*accr[mt][nt][2*i+1];
            if(bias){ v.x += bias[gn]; v.y += bias[gn+1]; }
            float* cp = C + (long)gm*ldc + gn;
            if(acc){ v.x += cp[0]; v.y += cp[1]; }
            *(float2*)cp = v;
        }
    }
}

// Fused GEMM+softmax: C = softmax_row(alpha * A @ B^T), K=64, N=256 exactly.
// Block computes 64 rows x 256 cols. 8 warps: wm(2) x wn(4), warp = 32 rows x 64 cols.
__global__ void __launch_bounds__(256,2) k_simsm(
    const float* __restrict__ A, int lda, long sAb, long sAh,
    const float* __restrict__ B, int ldb, long sBb, long sBh,
    float* __restrict__ C, int ldc, long sCb, long sCh,
    float alpha)
{
    int z = blockIdx.z; int hh = z & 7; int bb = z >> 3;
    A += (long)bb*sAb + (long)hh*sAh;
    B += (long)bb*sBb + (long)hh*sBh;
    C += (long)bb*sCb + (long)hh*sCh;
    __shared__ uint32_t As[64][20];
    __shared__ uint32_t Bs[256][20];
    __shared__ float red[64][4];
    int t = threadIdx.x;
    int lane = t & 31, warp = t >> 5;
    int wm = warp >> 2, wn = warp & 3;
    int r0 = blockIdx.x*64;
    int lrow = t >> 2, lk = (t & 3)*4;
    float acc[2][8][4];
    #pragma unroll
    for(int i=0;i<2;i++)
        #pragma unroll
        for(int j=0;j<8;j++)
            #pragma unroll
            for(int q=0;q<4;q++) acc[i][j][q]=0.f;
    for(int kt=0; kt<4; kt++){
        __syncthreads();
        *(uint4*)&As[lrow][lk] = cvt4(ldg4(A + (long)(r0+lrow)*lda + kt*16 + lk));
        #pragma unroll
        for(int i=0;i<4;i++)
            *(uint4*)&Bs[i*64+lrow][lk] = cvt4(ldg4(B + (long)(i*64+lrow)*ldb + kt*16 + lk));
        __syncthreads();
        #pragma unroll
        for(int ks=0;ks<2;ks++){
            int cc = ks*8 + (lane&3);
            uint32_t a[2][4], b[8][2];
            int rA = wm*32 + (lane>>2);
            #pragma unroll
            for(int mt=0;mt<2;mt++){
                a[mt][0]=As[rA+mt*16  ][cc];
                a[mt][1]=As[rA+mt*16+8][cc];
                a[mt][2]=As[rA+mt*16  ][cc+4];
                a[mt][3]=As[rA+mt*16+8][cc+4];
            }
            int rB = wn*64 + (lane>>2);
            #pragma unroll
            for(int nt=0;nt<8;nt++){
                b[nt][0]=Bs[rB+nt*8][cc];
                b[nt][1]=Bs[rB+nt*8][cc+4];
            }
            #pragma unroll
            for(int mt=0;mt<2;mt++)
                #pragma unroll
                for(int nt=0;nt<8;nt++)
                    mma8(acc[mt][nt], a[mt], b[nt]);
        }
    }
    int g = lane>>2, tq = lane&3;
    // --- row max ---
    float pm[2][2];
    #pragma unroll
    for(int mt=0;mt<2;mt++)
        #pragma unroll
        for(int i=0;i<2;i++){
            float m = -1e30f;
            #pragma unroll
            for(int nt=0;nt<8;nt++){
                acc[mt][nt][2*i]   *= alpha;
                acc[mt][nt][2*i+1] *= alpha;
                m = fmaxf(m, fmaxf(acc[mt][nt][2*i], acc[mt][nt][2*i+1]));
            }
            m = fmaxf(m, __shfl_xor_sync(0xffffffffu, m, 1));
            m = fmaxf(m, __shfl_xor_sync(0xffffffffu, m, 2));
            pm[mt][i] = m;
        }
    if(tq==0){
        #pragma unroll
        for(int mt=0;mt<2;mt++)
            #pragma unroll
            for(int i=0;i<2;i++)
                red[wm*32+mt*16+i*8+g][wn] = pm[mt][i];
    }
    __syncthreads();
    float rmax[2][2];
    #pragma unroll
    for(int mt=0;mt<2;mt++)
        #pragma unroll
        for(int i=0;i<2;i++){
            int rid = wm*32+mt*16+i*8+g;
            rmax[mt][i] = fmaxf(fmaxf(red[rid][0],red[rid][1]), fmaxf(red[rid][2],red[rid][3]));
        }
    __syncthreads();
    // --- exp + row sum ---
    float ps[2][2];
    #pragma unroll
    for(int mt=0;mt<2;mt++)
        #pragma unroll
        for(int i=0;i<2;i++){
            float s = 0.f;
            #pragma unroll
            for(int nt=0;nt<8;nt++){
                float e0 = __expf(acc[mt][nt][2*i]   - rmax[mt][i]);
                float e1 = __expf(acc[mt][nt][2*i+1] - rmax[mt][i]);
                acc[mt][nt][2*i]   = e0;
                acc[mt][nt][2*i+1] = e1;
                s += e0 + e1;
            }
            s += __shfl_xor_sync(0xffffffffu, s, 1);
            s += __shfl_xor_sync(0xffffffffu, s, 2);
            ps[mt][i] = s;
        }
    if(tq==0){
        #pragma unroll
        for(int mt=0;mt<2;mt++)
            #pragma unroll
            for(int i=0;i<2;i++)
                red[wm*32+mt*16+i*8+g][wn] = ps[mt][i];
    }
    __syncthreads();
    #pragma unroll
    for(int mt=0;mt<2;mt++)
        #pragma unroll
        for(int i=0;i<2;i++){
            int rid = wm*32+mt*16+i*8+g;
            float inv = 1.f/(red[rid][0]+red[rid][1]+red[rid][2]+red[rid][3]);
            long gm = r0 + rid;
            #pragma unroll
            for(int nt=0;nt<8;nt++){
                int gn = wn*64 + nt*8 + 2*tq;
                float2 v; v.x = acc[mt][nt][2*i]*inv; v.y = acc[mt][nt][2*i+1]*inv;
                *(float2*)(C + gm*ldc + gn) = v;
            }
        }
}

// C = alpha * A @ B  (NN), pinv epilogues:
//   cmode==1 : C = dconst*I - v
//   D != 0   : D = dconst*I - v   (in addition to C = v)
__global__ void __launch_bounds__(256,2) k_mma_nn(
    const float* __restrict__ A, int lda, long sAb, long sAh,
    const float* __restrict__ B, int ldb, long sBb, long sBh,
    float* __restrict__ C, int ldc, long sCb, long sCh,
    float* __restrict__ D, long sDb, long sDh,
    int M, int N, int K, float alpha, float dconst, int cmode)
{
    int z = blockIdx.z; int hh = z & 7; int bb = z >> 3;
    A += (long)bb*sAb + (long)hh*sAh;
    B += (long)bb*sBb + (long)hh*sBh;
    C += (long)bb*sCb + (long)hh*sCh;
    if(D) D += (long)bb*sDb + (long)hh*sDh;
    __shared__ uint32_t As[128][20];
    __shared__ uint32_t Bs[16][136];
    int t = threadIdx.x;
    int lane = t & 31, warp = t >> 5;
    int wm = warp >> 2, wn = warp & 3;
    int r0 = blockIdx.x*128, c0 = blockIdx.y*128;
    int lrow = t >> 2, lk = (t & 3)*4;      // A loader
    int bk = t >> 5, bn = (t & 31)*4;       // B loader: rows bk, bk+8
    const float* Ap0 = A + (long)(r0+lrow)*lda + lk;
    const float* Ap1 = A + (long)(r0+lrow+64)*lda + lk;
    const float* Bq0 = B + (long)bk*ldb + c0 + bn;
    const float* Bq1 = B + (long)(bk+8)*ldb + c0 + bn;
    bool mA0 = (r0+lrow)<M, mA1 = (r0+lrow+64)<M;
    bool mBn = (c0+bn)<N;
    const float4 z4 = make_float4(0.f,0.f,0.f,0.f);
    float4 pa0 = mA0?ldg4(Ap0):z4, pa1 = mA1?ldg4(Ap1):z4;
    float4 pb0 = mBn?ldg4(Bq0):z4, pb1 = mBn?ldg4(Bq1):z4;
    *(uint4*)&As[lrow][lk]    = cvt4(pa0);
    *(uint4*)&As[lrow+64][lk] = cvt4(pa1);
    *(uint4*)&Bs[bk][bn]      = cvt4(pb0);
    *(uint4*)&Bs[bk+8][bn]    = cvt4(pb1);
    float accr[4][4][4];
    #pragma unroll
    for(int i=0;i<4;i++)
        #pragma unroll
        for(int j=0;j<4;j++)
            #pragma unroll
            for(int q=0;q<4;q++) accr[i][j][q]=0.f;
    int nk = K >> 4;
    for(int kt=0; kt<nk; kt++){
        __syncthreads();
        if(kt+1<nk){
            long o = (long)(kt+1)*16;
            pa0 = mA0?ldg4(Ap0+o):z4; pa1 = mA1?ldg4(Ap1+o):z4;
            pb0 = mBn?ldg4(Bq0+o*ldb):z4; pb1 = mBn?ldg4(Bq1+o*ldb):z4;
        }
        #pragma unroll
        for(int ks=0;ks<2;ks++){
            int cc = ks*8 + (lane&3);
            uint32_t a[4][4], b[4][2];
            int rA = wm*64 + (lane>>2);
            #pragma unroll
            for(int mt=0;mt<4;mt++){
                a[mt][0]=As[rA+mt*16  ][cc];
                a[mt][1]=As[rA+mt*16+8][cc];
                a[mt][2]=As[rA+mt*16  ][cc+4];
                a[mt][3]=As[rA+mt*16+8][cc+4];
            }
            int nB = wn*32 + (lane>>2);
            #pragma unroll
            for(int nt=0;nt<4;nt++){
                b[nt][0]=Bs[cc  ][nB+nt*8];
                b[nt][1]=Bs[cc+4][nB+nt*8];
            }
            #pragma unroll
            for(int mt=0;mt<4;mt++)
                #pragma unroll
                for(int nt=0;nt<4;nt++)
                    mma8(accr[mt][nt], a[mt], b[nt]);
        }
        __syncthreads();
        if(kt+1<nk){
            *(uint4*)&As[lrow][lk]    = cvt4(pa0);
            *(uint4*)&As[lrow+64][lk] = cvt4(pa1);
            *(uint4*)&Bs[bk][bn]      = cvt4(pb0);
            *(uint4*)&Bs[bk+8][bn]    = cvt4(pb1);
        }
    }
    #pragma unroll
    for(int mt=0;mt<4;mt++)
    #pragma unroll
    for(int i=0;i<2;i++){
        int gm = r0 + wm*64 + mt*16 + i*8 + (lane>>2);
        if(gm>=M) continue;
        #pragma unroll
        for(int nt=0;nt<4;nt++){
            int gn = c0 + wn*32 + nt*8 + 2*(lane&3);
            float2 v;
            v.x = alpha*accr[mt][nt][2*i];
            v.y = alpha*accr[mt][nt][2*i+1];
            long o = (long)gm*ldc + gn;
            if(D){
                float2 dv;
                dv.x = ((gm==gn  )?dconst:0.f) - v.x;
                dv.y = ((gm==gn+1)?dconst:0.f) - v.y;
                *(float2*)(D+o) = dv;
            }
            if(cmode){
                v.x = ((gm==gn  )?dconst:0.f) - v.x;
                v.y = ((gm==gn+1)?dconst:0.f) - v.y;
            }
            *(float2*)(C+o) = v;
        }
    }
}

// C = alpha * A @ B  (NN fp32), 128x64 tile, BK=16, 8x4/thread. For N=64 GEMMs.
// Rows gm < rowLo are skipped (used for direct token-major writes).
__global__ void __launch_bounds__(256,2) k_gemm_nn_12864(
    const float* __restrict__ A, int lda, long sAb, long sAh,
    const float* __restrict__ B, int ldb, long sBb, long sBh,
    float* __restrict__ C, int ldc, long sCb, long sCh,
    int M, int N, int K, float alpha, int rowLo)
{
    int z = blockIdx.z; int hh = z & 7; int bb = z >> 3;
    A += (long)bb*sAb + (long)hh*sAh;
    B += (long)bb*sBb + (long)hh*sBh;
    C += (long)bb*sCb + (long)hh*sCh;
    __shared__ float As[2][16][132];
    __shared__ float Bs[2][16][68];
    int t = threadIdx.x;
    int tx = t & 15, ty = t >> 4;
    int r0 = blockIdx.x*128, c0 = blockIdx.y*64;
    int lm0 = t >> 2, lk0 = (t & 3)*4;
    int lm1 = lm0 + 64;
    int brow = t >> 4, bcs = t & 15;
    const float* Ap0 = A + (long)(r0+lm0)*lda + lk0;
    const float* Ap1 = A + (long)(r0+lm1)*lda + lk0;
    const float* Bp  = B + (long)brow*ldb + c0 + bcs*4;
    bool am0 = (r0+lm0) < M;
    bool am1 = (r0+lm1) < M;
    float4 ar0 = am0 ? ldg4(Ap0) : make_float4(0.f,0.f,0.f,0.f);
    float4 ar1 = am1 ? ldg4(Ap1) : make_float4(0.f,0.f,0.f,0.f);
    float4 br  = ldg4(Bp);
    As[0][lk0+0][lm0]=ar0.x; As[0][lk0+1][lm0]=ar0.y; As[0][lk0+2][lm0]=ar0.z; As[0][lk0+3][lm0]=ar0.w;
    As[0][lk0+0][lm1]=ar1.x; As[0][lk0+1][lm1]=ar1.y; As[0][lk0+2][lm1]=ar1.z; As[0][lk0+3][lm1]=ar1.w;
    *(float4*)&Bs[0][brow][bcs*4] = br;
    __syncthreads();
    float acc4[8][4];
    #pragma unroll
    for(int i=0;i<8;i++)
        #pragma unroll
        for(int j=0;j<4;j++) acc4[i][j]=0.f;
    int nk = K >> 4;
    int buf = 0;
    for(int kt=0; kt<nk; kt++){
        if(kt+1 < nk){
            ar0 = am0 ? ldg4(Ap0 + (kt+1)*16) : make_float4(0.f,0.f,0.f,0.f);
            ar1 = am1 ? ldg4(Ap1 + (kt+1)*16) : make_float4(0.f,0.f,0.f,0.f);
            br  = ldg4(Bp + (long)(kt+1)*16*ldb);
        }
        #pragma unroll
        for(int kk=0;kk<16;kk++){
            float a[8], b[4];
            *(float4*)(a)   = *(const float4*)&As[buf][kk][ty*4];
            *(float4*)(a+4) = *(const float4*)&As[buf][kk][64+ty*4];
            *(float4*)(b)   = *(const float4*)&Bs[buf][kk][tx*4];
            #pragma unroll
            for(int i=0;i<8;i++)
                #pragma unroll
                for(int j=0;j<4;j++)
                    acc4[i][j] = fmaf(a[i], b[j], acc4[i][j]);
        }
        if(kt+1 < nk){
            buf ^= 1;
            As[buf][lk0+0][lm0]=ar0.x; As[buf][lk0+1][lm0]=ar0.y; As[buf][lk0+2][lm0]=ar0.z; As[buf][lk0+3][lm0]=ar0.w;
            As[buf][lk0+0][lm1]=ar1.x; As[buf][lk0+1][lm1]=ar1.y; As[buf][lk0+2][lm1]=ar1.z; As[buf][lk0+3][lm1]=ar1.w;
            *(float4*)&Bs[buf][brow][bcs*4] = br;
            __syncthreads();
        }
    }
    #pragma unroll
    for(int gi=0; gi<2; gi++)
    #pragma unroll
    for(int i=0;i<4;i++){
        int gm = r0 + gi*64 + ty*4 + i;
        if(gm >= M || gm < rowLo) continue;
        int gn = c0 + tx*4;
        float4 v;
        v.x = alpha*acc4[gi*4+i][0];
        v.y = alpha*acc4[gi*4+i][1];
        v.z = alpha*acc4[gi*4+i][2];
        v.w = alpha*acc4[gi*4+i][3];
        *(float4*)(C + (long)gm*ldc + gn) = v;
    }
}

// ---------------- softmax over rows of length 4352, register-cached ----------------
__global__ void k_softmax4352(float* __restrict__ X){
    long row = blockIdx.x;
    float* x = X + row*4352;
    int t = threadIdx.x;
    __shared__ float red[256];
    float v[17]; float mx = -1e30f;
    #pragma unroll
    for(int i=0;i<17;i++){ v[i] = x[i*256+t]; mx = fmaxf(mx, v[i]); }
    red[t]=mx; __syncthreads();
    for(int k=128;k;k>>=1){ if(t<k) red[t]=fmaxf(red[t],red[t+k]); __syncthreads(); }
    mx = red[0]; __syncthreads();
    float s = 0.f;
    #pragma unroll
    for(int i=0;i<17;i++){ v[i] = __expf(v[i]-mx); s += v[i]; }
    red[t]=s; __syncthreads();
    for(int k=128;k;k>>=1){ if(t<k) red[t]+=red[t+k]; __syncthreads(); }
    float inv = 1.f/red[0];
    #pragma unroll
    for(int i=0;i<17;i++) x[i*256+t] = v[i]*inv;
}

// ---------------- landmarks (mean over 17 tokens), q scaled by 1/8 ----------------
__global__ void k_landmarks(const float* __restrict__ qkv, float* __restrict__ ql, float* __restrict__ kl){
    int idx = blockIdx.x;                   // b*8*256 + h*256 + mi
    int mi = idx % 256; int hh = (idx/256) & 7; int b = idx / (256*8);
    int dh = threadIdx.x;
    float sq=0.f, sk=0.f;
    for(int j=0;j<LSUB;j++){
        long tok = (long)mi*LSUB + j;
        const float* base = qkv + ((long)b*4352 + tok)*1536 + hh*64 + dh;
        sq += base[0];
        sk += base[512];
    }
    long o = (long)idx*64 + dh;
    ql[o] = sq * (0.125f/LSUB);
    kl[o] = sk * (1.0f/LSUB);
}

// ---------------- pinv scalar reductions ----------------
__global__ void k_scal_init(){ if(threadIdx.x < 2) g_scal[threadIdx.x] = 0.f; }

__global__ void k_rowsum_max(const float* __restrict__ X){
    long row = blockIdx.x;
    const float* x = X + row*256;
    int t = threadIdx.x;
    __shared__ float red[256];
    red[t] = fabsf(x[t]); __syncthreads();
    for(int k=128;k;k>>=1){ if(t<k) red[t]+=red[t+k]; __syncthreads(); }
    if(t==0) atomicMax((int*)&g_scal[0], __float_as_int(red[0]));
}

__global__ void k_colsum_max(const float* __restrict__ X){
    int b = blockIdx.x; int j = threadIdx.x;
    const float* x = X + (long)b*65536;
    float s = 0.f;
    for(int i=0;i<256;i++) s += fabsf(x[i*256+j]);
    __shared__ float red[256];
    red[j]=s; __syncthreads();
    for(int k=128;k;k>>=1){ if(j<k) red[j]=fmaxf(red[j],red[j+k]); __syncthreads(); }
    if(j==0) atomicMax((int*)&g_scal[1], __float_as_int(red[0]));
}

__global__ void k_tr_scale(const float* __restrict__ X, float* __restrict__ Z){
    long idx = (long)blockIdx.x*256 + threadIdx.x;
    if(idx >= 64L*65536) return;
    float inv = 1.f/(g_scal[0]*g_scal[1]);
    int j = (int)(idx & 255); int i = (int)((idx>>8) & 255); long b = idx >> 16;
    Z[idx] = X[(b<<16) + ((long)j<<8) + i] * inv;
}

// ---------------- residual depthwise conv (k=33), writes token-major into ac ----------------
__global__ void k_resconv2(const float* __restrict__ qkv, const float* __restrict__ w,
                           float* __restrict__ ac){
    int bh = blockIdx.y; int hh = bh & 7; int b = bh >> 3;
    int t0 = blockIdx.x*64;
    __shared__ float sv[96][65];
    __shared__ float sw[33];
    int t = threadIdx.x;
    if(t < 33) sw[t] = w[hh*33 + t];
    const float* vb = qkv + ((long)b*4352)*1536 + 1024 + hh*64;
    for(int i=t;i<96*64;i+=256){
        int tok = t0 - 16 + (i>>6); int dh = i&63;
        sv[i>>6][dh] = (tok>=0 && tok<4352) ? vb[(long)tok*1536 + dh] : 0.f;
    }
    __syncthreads();
    for(int i=t;i<64*64;i+=256){
        int lt = i>>6, dh = i&63;
        int tok = t0 + lt;
        if(tok < 255) continue;
        float s = 0.f;
        #pragma unroll
        for(int j=0;j<33;j++) s = fmaf(sw[j], sv[lt+j][dh], s);
        ac[((long)b*4097 + (tok-255))*512 + hh*64 + dh] += s;
    }
}

// ---------------- transposes token<->planar ----------------
__global__ void k_h2planar(const float* __restrict__ h, float* __restrict__ cnn){
    __shared__ float tile[32][33];
    int b = blockIdx.z;
    int c0 = blockIdx.x*32, p0 = blockIdx.y*32;
    int tx = threadIdx.x, ty = threadIdx.y;
    for(int i=ty;i<32;i+=8)
        tile[i][tx] = h[((long)b*4097 + 1 + p0+i)*512 + c0+tx];
    __syncthreads();
    for(int i=ty;i<32;i+=8)
        cnn[((long)b*512 + c0+i)*4096 + p0+tx] = tile[tx][i];
}

__global__ void k_planar2h(const float* __restrict__ yp, float* __restrict__ h2){
    __shared__ float tile[32][33];
    int b = blockIdx.z;
    int c0 = blockIdx.x*32, p0 = blockIdx.y*32;
    int tx = threadIdx.x, ty = threadIdx.y;
    for(int i=ty;i<32;i+=8)
        tile[i][tx] = yp[((long)b*512 + c0+i)*4096 + p0+tx];
    __syncthreads();
    for(int i=ty;i<32;i+=8)
        h2[((long)b*4097 + 1 + p0+i)*512 + c0+tx] = tile[tx][i];
}

__global__ void k_cls_copy(const float* __restrict__ h, float* __restrict__ h2){
    int idx = blockIdx.x*256 + threadIdx.x;
    if(idx >= 8*512) return;
    int b = idx >> 9, c = idx & 511;
    h2[(long)b*4097*512 + c] = h[(long)b*4097*512 + c];
}

// ---------------- fused 7x7 + 5x5 + 3x3 depthwise conv, planar ----------------
__global__ void k_dwconv(const float* __restrict__ cnn,
                         const float* __restrict__ w7, const float* __restrict__ b7,
                         const float* __restrict__ w5, const float* __restrict__ b5,
                         const float* __restrict__ w3, const float* __restrict__ b3,
                         float* __restrict__ yp){
    int bc = blockIdx.x; int c = bc & 511;
    __shared__ float pl[64][65];
    __shared__ float ww[84];
    const float* in = cnn + (long)bc*4096;
    int t = threadIdx.x;
    for(int i=t;i<4096;i+=256) pl[i>>6][i&63] = in[i];
    if(t < 49)      ww[t]      = w7[c*49 + t];
    else if(t < 74) ww[t]      = w5[c*25 + t - 49];
    else if(t < 83) ww[t]      = w3[c*9  + t - 74];
    __syncthreads();
    float bias = b7[c] + b5[c] + b3[c];
    for(int i=t;i<4096;i+=256){
        int y = i >> 6, x = i & 63;
        float s = pl[y][x] + bias;
        #pragma unroll
        for(int ky=0;ky<7;ky++){ int yy=y+ky-3; if((unsigned)yy>=64u) continue;
            #pragma unroll
            for(int kx=0;kx<7;kx++){ int xx=x+kx-3; if((unsigned)xx>=64u) continue;
                s = fmaf(ww[ky*7+kx], pl[yy][xx], s); } }
        #pragma unroll
        for(int ky=0;ky<5;ky++){ int yy=y+ky-2; if((unsigned)yy>=64u) continue;
            #pragma unroll
            for(int kx=0;kx<5;kx++){ int xx=x+kx-2; if((unsigned)xx>=64u) continue;
                s = fmaf(ww[49+ky*5+kx], pl[yy][xx], s); } }
        #pragma unroll
        for(int ky=0;ky<3;ky++){ int yy=y+ky-1; if((unsigned)yy>=64u) continue;
            #pragma unroll
            for(int kx=0;kx<3;kx++){ int xx=x+kx-1; if((unsigned)xx>=64u) continue;
                s = fmaf(ww[74+ky*3+kx], pl[yy][xx], s); } }
        yp[(long)bc*4096 + i] = s;
    }
}

// ---------------- final output: (cls[8,512], feat[8,4096,512]) ----------------
__global__ void k_writeout(const float* __restrict__ h2, float* __restrict__ out){
    long idx = (long)blockIdx.x*256 + threadIdx.x;
    if(idx >= 8L*512 + 8L*4096*512) return;
    if(idx < 8*512){
        int b = (int)(idx >> 9), c = (int)(idx & 511);
        out[idx] = h2[((long)b*4097)*512 + c];
    } else {
        long r = idx - 4096;
        int c = (int)(r & 511); long q = r >> 9; int t = (int)(q % 4096); int b = (int)(q / 4096);
        out[idx] = h2[((long)b*4097 + 1 + t)*512 + c];
    }
}

// ================= host side =================
struct Ptrs {
    float *h,*h2,*xp,*qkv,*ql,*kl,*sim1,*sim3,*a2,*zA,*zB,*xz,*t1,*t2,*a3v,*tmp2,*ac,*cnn,*yp;
};

static void get_ptrs(Ptrs& p){
    cudaGetSymbolAddress((void**)&p.h,    g_h);
    cudaGetSymbolAddress((void**)&p.h2,   g_h2);
    cudaGetSymbolAddress((void**)&p.xp,   g_xp);
    cudaGetSymbolAddress((void**)&p.qkv,  g_qkv);
    cudaGetSymbolAddress((void**)&p.ql,   g_ql);
    cudaGetSymbolAddress((void**)&p.kl,   g_kl);
    cudaGetSymbolAddress((void**)&p.sim1, g_sim1);
    cudaGetSymbolAddress((void**)&p.sim3, g_sim3);
    cudaGetSymbolAddress((void**)&p.a2,   g_a2);
    cudaGetSymbolAddress((void**)&p.zA,   g_zA);
    cudaGetSymbolAddress((void**)&p.zB,   g_zB);
    cudaGetSymbolAddress((void**)&p.xz,   g_xz);
    cudaGetSymbolAddress((void**)&p.t1,   g_t1);
    cudaGetSymbolAddress((void**)&p.t2,   g_t2);
    cudaGetSymbolAddress((void**)&p.a3v,  g_a3v);
    cudaGetSymbolAddress((void**)&p.tmp2, g_tmp2);
    cudaGetSymbolAddress((void**)&p.ac,   g_ac);
    cudaGetSymbolAddress((void**)&p.cnn,  g_cnn);
    cudaGetSymbolAddress((void**)&p.yp,   g_yp);
}

static void attention(Ptrs& p, float* hbuf,
                      const float* lng, const float* lnb,
                      const float* qkvw, const float* outw, const float* outb,
                      const float* resw)
{
    const long SQKV_B = 4352L*1536;      // batch-b stride in qkv
    const long SQL    = 256L*64;         // per-(b,h) stride in ql/kl
    const long SS1    = 4352L*256;       // per-(b,h) stride sim1
    const long SS3    = 256L*4352;       // per-(b,h) stride sim3
    const long SA2    = 65536L;
    const long SV64   = 256L*64;

    k_zero_pad<<<4080, 256>>>(p.xp);
    k_ln<<<8*4097, 256>>>(hbuf, lng, lnb, p.xp);

    // qkv = xp @ qkv_w^T   (34816 x 1536 x 512)
    k_mma_nt<<<dim3(272,12,1), 256>>>(p.xp, 512, 0,0, qkvw, 512, 0,0,
                                      p.qkv, 1536, 0,0, 34816, 1536, 512, 1.f, nullptr, 0);

    k_landmarks<<<64*256, 64>>>(p.qkv, p.ql, p.kl);

    // a1 = softmax((q*scale) @ k_l^T) fused : (4352 x 256) per (b,h)
    k_simsm<<<dim3(68,1,64), 256>>>(p.qkv, 1536, SQKV_B, 64,
                                    p.kl, 64, 8*SQL, SQL,
                                    p.sim1, 256, 8*SS1, SS1, 0.125f);

    // a2 = softmax(q_l @ k_l^T) fused : (256 x 256)
    k_simsm<<<dim3(4,1,64), 256>>>(p.ql, 64, 8*SQL, SQL,
                                   p.kl, 64, 8*SQL, SQL,
                                   p.a2, 256, 8*SA2, SA2, 1.f);

    // sim3 = q_l @ k^T : (256 x 4352 x 64)
    k_mma_nt<<<dim3(2,34,64), 256>>>(p.ql, 64, 8*SQL, SQL,
                                     p.qkv + 512, 1536, SQKV_B, 64,
                                     p.sim3, 4352, 8*SS3, SS3,
                                     256, 4352, 64, 1.f, nullptr, 0);
    k_softmax4352<<<64*256, 256>>>(p.sim3);

    // a3v = a3 @ v : (256 x 64 x 4352)
    k_gemm_nn_12864<<<dim3(2,1,64), 256>>>(p.sim3, 4352, 8*SS3, SS3,
                                           p.qkv + 1024, 1536, SQKV_B, 64,
                                           p.a3v, 64, 8*SV64, SV64,
                                           256, 64, 4352, 1.f, 0);

    // ---- Moore-Penrose pinv of a2 (6 iterations, idm fused in epilogues) ----
    k_scal_init<<<1, 32>>>();
    k_rowsum_max<<<64*256, 256>>>(p.a2);
    k_colsum_max<<<64, 256>>>(p.a2);
    k_tr_scale<<<16384, 256>>>(p.a2, p.zA);

    float* zc = p.zA; float* zn = p.zB;
    for(int it=0; it<6; it++){
        // xz = a2 @ z ; t1 = 7I - xz
        k_mma_nn<<<dim3(2,2,64), 256>>>(p.a2, 256, 8*SA2, SA2, zc, 256, 8*SA2, SA2,
                                        p.xz, 256, 8*SA2, SA2, p.t1, 8*SA2, SA2,
                                        256,256,256, 1.f, 7.f, 0);
        // t2 = 15I - xz @ t1
        k_mma_nn<<<dim3(2,2,64), 256>>>(p.xz, 256, 8*SA2, SA2, p.t1, 256, 8*SA2, SA2,
                                        p.t2, 256, 8*SA2, SA2, nullptr, 0,0,
                                        256,256,256, 1.f, 15.f, 1);
        // t1 = 13I - xz @ t2
        k_mma_nn<<<dim3(2,2,64), 256>>>(p.xz, 256, 8*SA2, SA2, p.t2, 256, 8*SA2, SA2,
                                        p.t1, 256, 8*SA2, SA2, nullptr, 0,0,
                                        256,256,256, 1.f, 13.f, 1);
        // zn = 0.25 * z @ t1
        k_mma_nn<<<dim3(2,2,64), 256>>>(zc, 256, 8*SA2, SA2, p.t1, 256, 8*SA2, SA2,
                                        zn, 256, 8*SA2, SA2, nullptr, 0,0,
                                        256,256,256, 0.25f, 0.f, 0);
        float* tmp = zc; zc = zn; zn = tmp;
    }

    // tmp2 = z @ a3v : (256 x 64 x 256)
    k_gemm_nn_12864<<<dim3(2,1,64), 256>>>(zc, 256, 8*SA2, SA2, p.a3v, 64, 8*SV64, SV64,
                                           p.tmp2, 64, 8*SV64, SV64, 256, 64, 256, 1.f, 0);
    // ac = a1 @ tmp2 written DIRECTLY token-major: (4352 x 64 x 256), rows >= 255 only
    k_gemm_nn_12864<<<dim3(34,1,64), 256>>>(p.sim1, 256, 8*SS1, SS1, p.tmp2, 64, 8*SV64, SV64,
                                            p.ac - 255*512, 512, 4097L*512, 64,
                                            4352, 64, 256, 1.f, 255);

    // residual depthwise conv (k=33 along sequence) added directly into ac
    k_resconv2<<<dim3(68,64), 256>>>(p.qkv, resw, p.ac);

    // hbuf += ac @ out_w^T + out_b
    k_mma_nt<<<dim3(257,4,1), 256>>>(p.ac, 512, 0,0, outw, 512, 0,0,
                                     hbuf, 512, 0,0, 32776, 512, 512, 1.f, outb, 1);
}

extern "C" void kernel_launch(void* const* d_in, const int* in_sizes, int n_in,
                              void* d_out, int out_size)
{
    const float* features = (const float*)d_in[0];
    const float* cls_tok  = (const float*)d_in[1];
    const float* ln1_g    = (const float*)d_in[2];
    const float* ln1_b    = (const float*)d_in[3];
    const float* qkv1_w   = (const float*)d_in[4];
    const float* out1_w   = (const float*)d_in[5];
    const float* out1_b   = (const float*)d_in[6];
    const float* res1_w   = (const float*)d_in[7];
    const float* p7_w     = (const float*)d_in[8];
    const float* p7_b     = (const float*)d_in[9];
    const float* p5_w     = (const float*)d_in[10];
    const float* p5_b     = (const float*)d_in[11];
    const float* p3_w     = (const float*)d_in[12];
    const float* p3_b     = (const float*)d_in[13];
    const float* ln2_g    = (const float*)d_in[14];
    const float* ln2_b    = (const float*)d_in[15];
    const float* qkv2_w   = (const float*)d_in[16];
    const float* out2_w   = (const float*)d_in[17];
    const float* out2_b   = (const float*)d_in[18];
    const float* res2_w   = (const float*)d_in[19];
    float* out = (float*)d_out;

    Ptrs p;
    get_ptrs(p);

    // h0 = [cls; features]  (4096 = 64^2, no extra duplication)
    k_build_h<<<65552, 256>>>(features, cls_tok);

    // block 1: h += nystrom(LN(h))
    attention(p, p.h, ln1_g, ln1_b, qkv1_w, out1_w, out1_b, res1_w);

    // CNN mixer on feature tokens (64x64 grid)
    k_h2planar<<<dim3(16,128,8), dim3(32,8)>>>(p.h, p.cnn);
    k_dwconv<<<4096, 256>>>(p.cnn, p7_w, p7_b, p5_w, p5_b, p3_w, p3_b, p.yp);
    k_planar2h<<<dim3(16,128,8), dim3(32,8)>>>(p.yp, p.h2);
    k_cls_copy<<<16, 256>>>(p.h, p.h2);

    // block 2: h2 += nystrom(LN(h2))
    attention(p, p.h2, ln2_g, ln2_b, qkv2_w, out2_w, out2_b, res2_w);

    // outputs: cls then features
    k_writeout<<<65552, 256>>>(p.h2, out);
}